// round 1
// baseline (speedup 1.0000x reference)
#include <cuda_runtime.h>
#include <math.h>

#define NN 3072
#define HEADS 4
#define IN_DIM 256
#define H1 128
#define H2 64
#define ADJW (NN/32)   // 96 words per row

// ---------------- scratch (device globals; no allocation allowed) ----------------
__device__ unsigned g_adjbits[NN * ADJW];              // 1.18 MB
__device__ float g_Whbuf[HEADS * NN * H1];             // 6.29 MB (layer2 uses first 4*3072*64)
__device__ float g_src[HEADS * NN], g_dst[HEADS * NN];
__device__ float g_e1s[HEADS * NN], g_e2s[HEADS * NN];
__device__ float g_e1d[HEADS * NN], g_e2d[HEADS * NN];
__device__ float g_maxdst[HEADS];
__device__ float g_hcat[NN * HEADS * H1];              // 6.29 MB
__device__ float g_h1[NN * H1];

// ---------------- adjacency bit-pack ----------------
__global__ void pack_adj_k(const int* __restrict__ adj) {
    int idx = blockIdx.x * blockDim.x + threadIdx.x;   // 0 .. N*N-1
    int v = adj[idx] > 0;
    unsigned m = __ballot_sync(0xffffffffu, v);
    if ((idx & 31) == 0) g_adjbits[idx >> 5] = m;
}

// ---------------- per-head GEMM: Wh[h] = X @ W[h]  ----------------
// grid (N/64, F/64, HEADS), block 256
__global__ __launch_bounds__(256) void gemm_heads_k(
    const float* __restrict__ X, const float* __restrict__ W,
    float* __restrict__ out, int K, int F)
{
    int h = blockIdx.z;
    int m0 = blockIdx.x * 64, n0 = blockIdx.y * 64;
    const float* Wp = W + (size_t)h * K * F;
    float* Op = out + (size_t)h * NN * F;
    __shared__ float Xs[64][17];
    __shared__ __align__(16) float Ws[16][64];
    int tid = threadIdx.x, ty = tid / 16, tx = tid % 16;
    float acc[4][4] = {};
    for (int kt = 0; kt < K; kt += 16) {
        int r = tid >> 2, c = (tid & 3) * 4;
        float4 xv = *(const float4*)&X[(size_t)(m0 + r) * K + kt + c];
        Xs[r][c] = xv.x; Xs[r][c + 1] = xv.y; Xs[r][c + 2] = xv.z; Xs[r][c + 3] = xv.w;
        int r2 = tid >> 4, c2 = (tid & 15) * 4;
        *(float4*)&Ws[r2][c2] = *(const float4*)&Wp[(size_t)(kt + r2) * F + n0 + c2];
        __syncthreads();
#pragma unroll
        for (int k = 0; k < 16; k++) {
            float a[4], b[4];
#pragma unroll
            for (int i = 0; i < 4; i++) a[i] = Xs[ty * 4 + i][k];
#pragma unroll
            for (int j = 0; j < 4; j++) b[j] = Ws[k][tx * 4 + j];
#pragma unroll
            for (int i = 0; i < 4; i++)
#pragma unroll
                for (int j = 0; j < 4; j++) acc[i][j] = fmaf(a[i], b[j], acc[i][j]);
        }
        __syncthreads();
    }
#pragma unroll
    for (int i = 0; i < 4; i++) {
        float4 v = make_float4(acc[i][0], acc[i][1], acc[i][2], acc[i][3]);
        *(float4*)&Op[(size_t)(m0 + ty * 4 + i) * F + n0 + tx * 4] = v;
    }
}

// ---------------- src/dst projections: one warp per (h,n) ----------------
__global__ void srcdst_k(const float* __restrict__ Wh, const float* __restrict__ as,
                         const float* __restrict__ ad, int F)
{
    int w = (blockIdx.x * blockDim.x + threadIdx.x) >> 5;
    int lane = threadIdx.x & 31;
    if (w >= HEADS * NN) return;
    int h = w / NN;
    const float* row = Wh + (size_t)w * F;
    float ss = 0.f, dd = 0.f;
    for (int f = lane; f < F; f += 32) {
        float v = row[f];
        ss = fmaf(v, as[h * F + f], ss);
        dd = fmaf(v, ad[h * F + f], dd);
    }
#pragma unroll
    for (int o = 16; o; o >>= 1) {
        ss += __shfl_xor_sync(0xffffffffu, ss, o);
        dd += __shfl_xor_sync(0xffffffffu, dd, o);
    }
    if (!lane) { g_src[w] = ss; g_dst[w] = dd; }
}

// ---------------- per-head max(dst) ----------------
__global__ void maxdst_k() {
    int h = blockIdx.x;
    float m = -1e30f;
    for (int n = threadIdx.x; n < NN; n += 256) m = fmaxf(m, g_dst[h * NN + n]);
    __shared__ float sm[256];
    sm[threadIdx.x] = m; __syncthreads();
    for (int s = 128; s; s >>= 1) {
        if (threadIdx.x < (unsigned)s) sm[threadIdx.x] = fmaxf(sm[threadIdx.x], sm[threadIdx.x + s]);
        __syncthreads();
    }
    if (!threadIdx.x) g_maxdst[h] = sm[0];
}

// ---------------- factored exps ----------------
__global__ void exps_k() {
    int i = blockIdx.x * blockDim.x + threadIdx.x;
    if (i >= HEADS * NN) return;
    int h = i / NN;
    float s = g_src[i], d = g_dst[i];
    float x = s + g_maxdst[h];
    float c = x > 0.f ? x : 0.2f * x;   // c_i >= max_j leaky(src_i + dst_j)
    g_e1s[i] = expf(s - c);
    g_e2s[i] = expf(0.2f * s - c);
    g_e1d[i] = expf(d);
    g_e2d[i] = expf(0.2f * d);
}

// ---------------- fused attention + aggregation ----------------
// out row (m): elu( (sum_j p_unnorm(m,j) * Wh[j,:]) / sum_j p_unnorm(m,j) )
// grid (N/32, HEADS), block 256
template <int F>
__global__ __launch_bounds__(256) void attn_k(const float* __restrict__ Wh,
                                              float* __restrict__ hcat)
{
    constexpr int BM = 32, BK = 64, TN = F / 32;
    int h = blockIdx.y, m0 = blockIdx.x * BM;
    __shared__ float Ps[BM][BK + 1];
    __shared__ __align__(16) float Whs[BK][F];
    __shared__ float dje1[BK], dje2[BK], djd[BK];
    __shared__ float rsum[BM];
    int tid = threadIdx.x;
    int pr = tid >> 3, pc0 = (tid & 7) * 8;
    int base = h * NN;
    float E1s = g_e1s[base + m0 + pr];
    float E2s = g_e2s[base + m0 + pr];
    float srcv = g_src[base + m0 + pr];
    int ty = tid >> 5, lane = tid & 31;
    float acc[4][TN] = {};
    float psum = 0.f;
    const float* Whh = Wh + (size_t)base * F;
    if (tid < BM) rsum[tid] = 0.f;

    for (int kt = 0; kt < NN; kt += BK) {
        __syncthreads();
        {
            const float4* s4 = (const float4*)(Whh + (size_t)kt * F);
            float4* d4 = (float4*)&Whs[0][0];
#pragma unroll
            for (int i = tid; i < BK * F / 4; i += 256) d4[i] = s4[i];
        }
        if (tid < BK) {
            dje1[tid] = g_e1d[base + kt + tid];
            dje2[tid] = g_e2d[base + kt + tid];
            djd[tid]  = g_dst[base + kt + tid];
        }
        __syncthreads();
        // build P tile (unnormalized softmax numerators, masked)
        unsigned bits = g_adjbits[(size_t)(m0 + pr) * ADJW + ((kt + pc0) >> 5)] >> (pc0 & 31);
#pragma unroll
        for (int c = 0; c < 8; c++) {
            int j = pc0 + c;
            float x = srcv + djd[j];
            float p = (x > 0.f) ? E1s * dje1[j] : E2s * dje2[j];
            p = ((bits >> c) & 1u) ? p : 0.f;
            Ps[pr][j] = p;
            psum += p;
        }
        __syncthreads();
        // GEMM accumulate: acc += Ps[rows][k] * Whs[k][cols]
#pragma unroll 16
        for (int k = 0; k < BK; k++) {
            float a[4];
#pragma unroll
            for (int i = 0; i < 4; i++) a[i] = Ps[ty * 4 + i][k];
            const float* wrow = &Whs[k][lane * TN];
#pragma unroll
            for (int j = 0; j < TN; j++) {
                float b = wrow[j];
#pragma unroll
                for (int i = 0; i < 4; i++) acc[i][j] = fmaf(a[i], b, acc[i][j]);
            }
        }
    }
    atomicAdd(&rsum[pr], psum);
    __syncthreads();
    constexpr int CAT = HEADS * F;
#pragma unroll
    for (int i = 0; i < 4; i++) {
        int row = ty * 4 + i;
        float inv = 1.f / rsum[row];
#pragma unroll
        for (int j = 0; j < TN; j++) {
            float v = acc[i][j] * inv;
            v = v > 0.f ? v : expm1f(v);   // elu
            hcat[(size_t)(m0 + row) * CAT + h * F + lane * TN + j] = v;
        }
    }
}

// ---------------- combine: out = relu( elu(A@LIN) + B@RES ) ----------------
// grid (N/64, FOUT/64), block 256
__global__ __launch_bounds__(256) void combine_k(
    const float* __restrict__ A, int KA, const float* __restrict__ LIN,
    const float* __restrict__ B, int KB, const float* __restrict__ RES,
    float* __restrict__ out, int FOUT)
{
    int m0 = blockIdx.x * 64, n0 = blockIdx.y * 64;
    __shared__ float Xs[64][17];
    __shared__ __align__(16) float Ws[16][64];
    int tid = threadIdx.x, ty = tid / 16, tx = tid % 16;
    float acc[4][4] = {};
    // pass 1: A @ LIN
    for (int kt = 0; kt < KA; kt += 16) {
        int r = tid >> 2, c = (tid & 3) * 4;
        float4 xv = *(const float4*)&A[(size_t)(m0 + r) * KA + kt + c];
        Xs[r][c] = xv.x; Xs[r][c + 1] = xv.y; Xs[r][c + 2] = xv.z; Xs[r][c + 3] = xv.w;
        int r2 = tid >> 4, c2 = (tid & 15) * 4;
        *(float4*)&Ws[r2][c2] = *(const float4*)&LIN[(size_t)(kt + r2) * FOUT + n0 + c2];
        __syncthreads();
#pragma unroll
        for (int k = 0; k < 16; k++) {
            float a[4], b[4];
#pragma unroll
            for (int i = 0; i < 4; i++) a[i] = Xs[ty * 4 + i][k];
#pragma unroll
            for (int j = 0; j < 4; j++) b[j] = Ws[k][tx * 4 + j];
#pragma unroll
            for (int i = 0; i < 4; i++)
#pragma unroll
                for (int j = 0; j < 4; j++) acc[i][j] = fmaf(a[i], b[j], acc[i][j]);
        }
        __syncthreads();
    }
    // elu
#pragma unroll
    for (int i = 0; i < 4; i++)
#pragma unroll
        for (int j = 0; j < 4; j++)
            acc[i][j] = acc[i][j] > 0.f ? acc[i][j] : expm1f(acc[i][j]);
    // pass 2: += B @ RES
    for (int kt = 0; kt < KB; kt += 16) {
        int r = tid >> 2, c = (tid & 3) * 4;
        float4 xv = *(const float4*)&B[(size_t)(m0 + r) * KB + kt + c];
        Xs[r][c] = xv.x; Xs[r][c + 1] = xv.y; Xs[r][c + 2] = xv.z; Xs[r][c + 3] = xv.w;
        int r2 = tid >> 4, c2 = (tid & 15) * 4;
        *(float4*)&Ws[r2][c2] = *(const float4*)&RES[(size_t)(kt + r2) * FOUT + n0 + c2];
        __syncthreads();
#pragma unroll
        for (int k = 0; k < 16; k++) {
            float a[4], b[4];
#pragma unroll
            for (int i = 0; i < 4; i++) a[i] = Xs[ty * 4 + i][k];
#pragma unroll
            for (int j = 0; j < 4; j++) b[j] = Ws[k][tx * 4 + j];
#pragma unroll
            for (int i = 0; i < 4; i++)
#pragma unroll
                for (int j = 0; j < 4; j++) acc[i][j] = fmaf(a[i], b[j], acc[i][j]);
        }
        __syncthreads();
    }
    // relu + store
#pragma unroll
    for (int i = 0; i < 4; i++) {
        float4 v;
        v.x = fmaxf(acc[i][0], 0.f); v.y = fmaxf(acc[i][1], 0.f);
        v.z = fmaxf(acc[i][2], 0.f); v.w = fmaxf(acc[i][3], 0.f);
        *(float4*)&out[(size_t)(m0 + ty * 4 + i) * FOUT + n0 + tx * 4] = v;
    }
}

// ---------------- host launcher ----------------
extern "C" void kernel_launch(void* const* d_in, const int* in_sizes, int n_in,
                              void* d_out, int out_size)
{
    const float* x    = (const float*)d_in[0];
    const int*   adj  = (const int*)d_in[1];
    const float* W1   = (const float*)d_in[2];
    const float* a1s  = (const float*)d_in[3];
    const float* a1d  = (const float*)d_in[4];
    const float* lin1 = (const float*)d_in[5];
    const float* res1 = (const float*)d_in[6];
    const float* W2   = (const float*)d_in[7];
    const float* a2s  = (const float*)d_in[8];
    const float* a2d  = (const float*)d_in[9];
    const float* lin2 = (const float*)d_in[10];
    const float* res2 = (const float*)d_in[11];
    float* out = (float*)d_out;

    float *whbuf, *hcat, *h1;
    cudaGetSymbolAddress((void**)&whbuf, g_Whbuf);
    cudaGetSymbolAddress((void**)&hcat,  g_hcat);
    cudaGetSymbolAddress((void**)&h1,    g_h1);

    // adjacency bitmask (once per launch; deterministic)
    pack_adj_k<<<NN * NN / 256, 256>>>(adj);

    // ---- layer 1 ----
    gemm_heads_k<<<dim3(NN / 64, H1 / 64, HEADS), 256>>>(x, W1, whbuf, IN_DIM, H1);
    srcdst_k<<<HEADS * NN * 32 / 256, 256>>>(whbuf, a1s, a1d, H1);
    maxdst_k<<<HEADS, 256>>>();
    exps_k<<<(HEADS * NN + 255) / 256, 256>>>();
    attn_k<H1><<<dim3(NN / 32, HEADS), 256>>>(whbuf, hcat);
    combine_k<<<dim3(NN / 64, H1 / 64), 256>>>(hcat, HEADS * H1, lin1, x, IN_DIM, res1, h1, H1);

    // ---- layer 2 ----
    gemm_heads_k<<<dim3(NN / 64, H2 / 64, HEADS), 256>>>(h1, W2, whbuf, H1, H2);
    srcdst_k<<<HEADS * NN * 32 / 256, 256>>>(whbuf, a2s, a2d, H2);
    maxdst_k<<<HEADS, 256>>>();
    exps_k<<<(HEADS * NN + 255) / 256, 256>>>();
    attn_k<H2><<<dim3(NN / 32, HEADS), 256>>>(whbuf, hcat);
    combine_k<<<dim3(NN / 64, H2 / 64), 256>>>(hcat, HEADS * H2, lin2, h1, H1, res2, out, H2);
}

// round 2
// speedup vs baseline: 1.0885x; 1.0885x over previous
#include <cuda_runtime.h>
#include <math.h>

#define NN 3072
#define HEADS 4
#define IN_DIM 256
#define H1 128
#define H2 64
#define ADJW (NN/32)   // 96 words per row

// ---------------- scratch (device globals; no allocation allowed) ----------------
__device__ unsigned g_adjbits[NN * ADJW];              // 1.18 MB
__device__ float g_Whbuf[HEADS * NN * H1];             // 6.29 MB
__device__ float g_src[HEADS * NN], g_dst[HEADS * NN];
__device__ float g_e1s[HEADS * NN], g_e2s[HEADS * NN];
__device__ float g_e1d[HEADS * NN], g_e2d[HEADS * NN];
__device__ unsigned g_maxenc[HEADS];
__device__ float g_hcat[NN * HEADS * H1];              // 6.29 MB
__device__ float g_h1[NN * H1];

// order-preserving float->uint encode (for atomicMax)
__device__ __forceinline__ unsigned enc_f(float v) {
    int b = __float_as_int(v);
    return b >= 0 ? ((unsigned)b | 0x80000000u) : (unsigned)(~b);
}
__device__ __forceinline__ float dec_f(unsigned e) {
    return (e & 0x80000000u) ? __uint_as_float(e & 0x7fffffffu)
                             : __uint_as_float(~e);
}

__device__ __forceinline__ unsigned long long pack_dup(float x) {
    unsigned long long r;
    asm("mov.b64 %0, {%1, %1};" : "=l"(r) : "f"(x));
    return r;
}

// ---------------- adjacency bit-pack ----------------
__global__ void pack_adj_k(const int* __restrict__ adj) {
    int idx = blockIdx.x * blockDim.x + threadIdx.x;
    int v = adj[idx] > 0;
    unsigned m = __ballot_sync(0xffffffffu, v);
    if ((idx & 31) == 0) g_adjbits[idx >> 5] = m;
}

// ---------------- per-head GEMM: Wh[h] = X @ W[h] ----------------
__global__ __launch_bounds__(256) void gemm_heads_k(
    const float* __restrict__ X, const float* __restrict__ W,
    float* __restrict__ out, int K, int F)
{
    int h = blockIdx.z;
    int m0 = blockIdx.x * 64, n0 = blockIdx.y * 64;
    const float* Wp = W + (size_t)h * K * F;
    float* Op = out + (size_t)h * NN * F;
    __shared__ float Xs[64][17];
    __shared__ __align__(16) float Ws[16][64];
    int tid = threadIdx.x, ty = tid / 16, tx = tid % 16;
    float acc[4][4] = {};
    for (int kt = 0; kt < K; kt += 16) {
        int r = tid >> 2, c = (tid & 3) * 4;
        float4 xv = *(const float4*)&X[(size_t)(m0 + r) * K + kt + c];
        Xs[r][c] = xv.x; Xs[r][c + 1] = xv.y; Xs[r][c + 2] = xv.z; Xs[r][c + 3] = xv.w;
        int r2 = tid >> 4, c2 = (tid & 15) * 4;
        *(float4*)&Ws[r2][c2] = *(const float4*)&Wp[(size_t)(kt + r2) * F + n0 + c2];
        __syncthreads();
#pragma unroll
        for (int k = 0; k < 16; k++) {
            float a[4], b[4];
#pragma unroll
            for (int i = 0; i < 4; i++) a[i] = Xs[ty * 4 + i][k];
#pragma unroll
            for (int j = 0; j < 4; j++) b[j] = Ws[k][tx * 4 + j];
#pragma unroll
            for (int i = 0; i < 4; i++)
#pragma unroll
                for (int j = 0; j < 4; j++) acc[i][j] = fmaf(a[i], b[j], acc[i][j]);
        }
        __syncthreads();
    }
#pragma unroll
    for (int i = 0; i < 4; i++) {
        float4 v = make_float4(acc[i][0], acc[i][1], acc[i][2], acc[i][3]);
        *(float4*)&Op[(size_t)(m0 + ty * 4 + i) * F + n0 + tx * 4] = v;
    }
}

// ---------------- src/dst projections + per-head max(dst) ----------------
__global__ void srcdst_k(const float* __restrict__ Wh, const float* __restrict__ as,
                         const float* __restrict__ ad, int F)
{
    int w = (blockIdx.x * blockDim.x + threadIdx.x) >> 5;
    int lane = threadIdx.x & 31;
    if (w >= HEADS * NN) return;
    int h = w / NN;
    const float* row = Wh + (size_t)w * F;
    float ss = 0.f, dd = 0.f;
    for (int f = lane; f < F; f += 32) {
        float v = row[f];
        ss = fmaf(v, as[h * F + f], ss);
        dd = fmaf(v, ad[h * F + f], dd);
    }
#pragma unroll
    for (int o = 16; o; o >>= 1) {
        ss += __shfl_xor_sync(0xffffffffu, ss, o);
        dd += __shfl_xor_sync(0xffffffffu, dd, o);
    }
    if (!lane) {
        g_src[w] = ss; g_dst[w] = dd;
        atomicMax(&g_maxenc[h], enc_f(dd));
    }
}

// ---------------- factored exps ----------------
__global__ void exps_k() {
    int i = blockIdx.x * blockDim.x + threadIdx.x;
    if (i >= HEADS * NN) return;
    int h = i / NN;
    float s = g_src[i], d = g_dst[i];
    float x = s + dec_f(g_maxenc[h]);
    float c = x > 0.f ? x : 0.2f * x;   // c_i >= max_j leaky(src_i + dst_j)
    g_e1s[i] = expf(s - c);
    g_e2s[i] = expf(0.2f * s - c);
    g_e1d[i] = expf(d);
    g_e2d[i] = expf(0.2f * d);
}

// ---------------- fused attention + aggregation (FFMA2) ----------------
// grid (N/32, HEADS), block 128: 4 warps x 8 rows; lanes cover F cols (TN each)
template <int F>
__global__ __launch_bounds__(128) void attn_k(const float* __restrict__ Wh,
                                              float* __restrict__ hcat)
{
    constexpr int BM = 32, BK = 64;
    constexpr int TN = F / 32;      // 4 (F=128) or 2 (F=64)
    constexpr int NP = TN / 2;      // packed f32x2 per row: 2 or 1
    int h = blockIdx.y, m0 = blockIdx.x * BM;
    __shared__ float Ps[BM][BK + 4];              // +4: rows 16B-aligned for LDS.128
    __shared__ __align__(16) float Whs[BK][F];
    __shared__ float dje1[BK], dje2[BK], djd[BK];
    __shared__ float rsum[BM];
    int tid = threadIdx.x;
    int pr = tid >> 2, pc0 = (tid & 3) * 16;      // P-build: 32 rows x 4x16 cols
    int base = h * NN;
    float E1s = g_e1s[base + m0 + pr];
    float E2s = g_e2s[base + m0 + pr];
    float srcv = g_src[base + m0 + pr];
    int warp = tid >> 5, lane = tid & 31;
    unsigned long long acc[8][NP] = {};
    float psum = 0.f;
    const float* Whh = Wh + (size_t)base * F;
    if (tid < BM) rsum[tid] = 0.f;

    for (int kt = 0; kt < NN; kt += BK) {
        __syncthreads();
        {
            const float4* s4 = (const float4*)(Whh + (size_t)kt * F);
            float4* d4 = (float4*)&Whs[0][0];
#pragma unroll
            for (int i = tid; i < BK * F / 4; i += 128) d4[i] = s4[i];
        }
        if (tid < BK) {
            dje1[tid] = g_e1d[base + kt + tid];
            dje2[tid] = g_e2d[base + kt + tid];
            djd[tid]  = g_dst[base + kt + tid];
        }
        __syncthreads();
        // build P tile (unnormalized, masked)
        unsigned bits = g_adjbits[(size_t)(m0 + pr) * ADJW + ((kt + pc0) >> 5)] >> (pc0 & 31);
#pragma unroll
        for (int c = 0; c < 16; c++) {
            int j = pc0 + c;
            float x = srcv + djd[j];
            float p = (x > 0.f) ? E1s * dje1[j] : E2s * dje2[j];
            p = ((bits >> c) & 1u) ? p : 0.f;
            Ps[pr][j] = p;
            psum += p;
        }
        __syncthreads();
        // acc += Ps[rows][k] * Whs[k][cols]   (packed f32x2)
#pragma unroll 2
        for (int k = 0; k < BK; k += 4) {
            float4 af[8];
#pragma unroll
            for (int i = 0; i < 8; i++)
                af[i] = *(const float4*)&Ps[warp * 8 + i][k];
#pragma unroll
            for (int kk = 0; kk < 4; kk++) {
                unsigned long long b[NP];
                const unsigned long long* bp =
                    (const unsigned long long*)&Whs[k + kk][lane * TN];
#pragma unroll
                for (int j = 0; j < NP; j++) b[j] = bp[j];
#pragma unroll
                for (int i = 0; i < 8; i++) {
                    float av = (kk == 0) ? af[i].x : (kk == 1) ? af[i].y
                             : (kk == 2) ? af[i].z : af[i].w;
                    unsigned long long a2 = pack_dup(av);
#pragma unroll
                    for (int j = 0; j < NP; j++)
                        asm("fma.rn.f32x2 %0, %1, %2, %0;"
                            : "+l"(acc[i][j]) : "l"(a2), "l"(b[j]));
                }
            }
        }
    }
    atomicAdd(&rsum[pr], psum);
    __syncthreads();
    constexpr int CAT = HEADS * F;
#pragma unroll
    for (int i = 0; i < 8; i++) {
        int row = warp * 8 + i;
        float inv = 1.f / rsum[row];
        float* orow = &hcat[(size_t)(m0 + row) * CAT + h * F + lane * TN];
#pragma unroll
        for (int j = 0; j < NP; j++) {
            float2 v = *(float2*)&acc[i][j];
            float v0 = v.x * inv; v0 = v0 > 0.f ? v0 : expm1f(v0);
            float v1 = v.y * inv; v1 = v1 > 0.f ? v1 : expm1f(v1);
            orow[2 * j]     = v0;
            orow[2 * j + 1] = v1;
        }
    }
}

// ---------------- combine: out = relu( elu(A@LIN) + B@RES ) ----------------
__global__ __launch_bounds__(256) void combine_k(
    const float* __restrict__ A, int KA, const float* __restrict__ LIN,
    const float* __restrict__ B, int KB, const float* __restrict__ RES,
    float* __restrict__ out, int FOUT)
{
    int m0 = blockIdx.x * 64, n0 = blockIdx.y * 64;
    __shared__ float Xs[64][17];
    __shared__ __align__(16) float Ws[16][64];
    int tid = threadIdx.x, ty = tid / 16, tx = tid % 16;
    float acc[4][4] = {};
    for (int kt = 0; kt < KA; kt += 16) {
        int r = tid >> 2, c = (tid & 3) * 4;
        float4 xv = *(const float4*)&A[(size_t)(m0 + r) * KA + kt + c];
        Xs[r][c] = xv.x; Xs[r][c + 1] = xv.y; Xs[r][c + 2] = xv.z; Xs[r][c + 3] = xv.w;
        int r2 = tid >> 4, c2 = (tid & 15) * 4;
        *(float4*)&Ws[r2][c2] = *(const float4*)&LIN[(size_t)(kt + r2) * FOUT + n0 + c2];
        __syncthreads();
#pragma unroll
        for (int k = 0; k < 16; k++) {
            float a[4], b[4];
#pragma unroll
            for (int i = 0; i < 4; i++) a[i] = Xs[ty * 4 + i][k];
#pragma unroll
            for (int j = 0; j < 4; j++) b[j] = Ws[k][tx * 4 + j];
#pragma unroll
            for (int i = 0; i < 4; i++)
#pragma unroll
                for (int j = 0; j < 4; j++) acc[i][j] = fmaf(a[i], b[j], acc[i][j]);
        }
        __syncthreads();
    }
#pragma unroll
    for (int i = 0; i < 4; i++)
#pragma unroll
        for (int j = 0; j < 4; j++)
            acc[i][j] = acc[i][j] > 0.f ? acc[i][j] : expm1f(acc[i][j]);
    for (int kt = 0; kt < KB; kt += 16) {
        int r = tid >> 2, c = (tid & 3) * 4;
        float4 xv = *(const float4*)&B[(size_t)(m0 + r) * KB + kt + c];
        Xs[r][c] = xv.x; Xs[r][c + 1] = xv.y; Xs[r][c + 2] = xv.z; Xs[r][c + 3] = xv.w;
        int r2 = tid >> 4, c2 = (tid & 15) * 4;
        *(float4*)&Ws[r2][c2] = *(const float4*)&RES[(size_t)(kt + r2) * FOUT + n0 + c2];
        __syncthreads();
#pragma unroll
        for (int k = 0; k < 16; k++) {
            float a[4], b[4];
#pragma unroll
            for (int i = 0; i < 4; i++) a[i] = Xs[ty * 4 + i][k];
#pragma unroll
            for (int j = 0; j < 4; j++) b[j] = Ws[k][tx * 4 + j];
#pragma unroll
            for (int i = 0; i < 4; i++)
#pragma unroll
                for (int j = 0; j < 4; j++) acc[i][j] = fmaf(a[i], b[j], acc[i][j]);
        }
        __syncthreads();
    }
#pragma unroll
    for (int i = 0; i < 4; i++) {
        float4 v;
        v.x = fmaxf(acc[i][0], 0.f); v.y = fmaxf(acc[i][1], 0.f);
        v.z = fmaxf(acc[i][2], 0.f); v.w = fmaxf(acc[i][3], 0.f);
        *(float4*)&out[(size_t)(m0 + ty * 4 + i) * FOUT + n0 + tx * 4] = v;
    }
}

// ---------------- host launcher ----------------
extern "C" void kernel_launch(void* const* d_in, const int* in_sizes, int n_in,
                              void* d_out, int out_size)
{
    const float* x    = (const float*)d_in[0];
    const int*   adj  = (const int*)d_in[1];
    const float* W1   = (const float*)d_in[2];
    const float* a1s  = (const float*)d_in[3];
    const float* a1d  = (const float*)d_in[4];
    const float* lin1 = (const float*)d_in[5];
    const float* res1 = (const float*)d_in[6];
    const float* W2   = (const float*)d_in[7];
    const float* a2s  = (const float*)d_in[8];
    const float* a2d  = (const float*)d_in[9];
    const float* lin2 = (const float*)d_in[10];
    const float* res2 = (const float*)d_in[11];
    float* out = (float*)d_out;

    float *whbuf, *hcat, *h1;
    void *maxenc;
    cudaGetSymbolAddress((void**)&whbuf, g_Whbuf);
    cudaGetSymbolAddress((void**)&hcat,  g_hcat);
    cudaGetSymbolAddress((void**)&h1,    g_h1);
    cudaGetSymbolAddress(&maxenc, g_maxenc);

    pack_adj_k<<<NN * NN / 256, 256>>>(adj);

    // ---- layer 1 ----
    cudaMemsetAsync(maxenc, 0, HEADS * sizeof(unsigned));
    gemm_heads_k<<<dim3(NN / 64, H1 / 64, HEADS), 256>>>(x, W1, whbuf, IN_DIM, H1);
    srcdst_k<<<HEADS * NN * 32 / 256, 256>>>(whbuf, a1s, a1d, H1);
    exps_k<<<(HEADS * NN + 255) / 256, 256>>>();
    attn_k<H1><<<dim3(NN / 32, HEADS), 128>>>(whbuf, hcat);
    combine_k<<<dim3(NN / 64, H1 / 64), 256>>>(hcat, HEADS * H1, lin1, x, IN_DIM, res1, h1, H1);

    // ---- layer 2 ----
    cudaMemsetAsync(maxenc, 0, HEADS * sizeof(unsigned));
    gemm_heads_k<<<dim3(NN / 64, H2 / 64, HEADS), 256>>>(h1, W2, whbuf, H1, H2);
    srcdst_k<<<HEADS * NN * 32 / 256, 256>>>(whbuf, a2s, a2d, H2);
    exps_k<<<(HEADS * NN + 255) / 256, 256>>>();
    attn_k<H2><<<dim3(NN / 32, HEADS), 128>>>(whbuf, hcat);
    combine_k<<<dim3(NN / 64, H2 / 64), 256>>>(hcat, HEADS * H2, lin2, h1, H1, res2, out, H2);
}

// round 4
// speedup vs baseline: 1.4626x; 1.3437x over previous
#include <cuda_runtime.h>
#include <math.h>
#include <cstdint>

#define NN 3072
#define HEADS 4
#define IN_DIM 256
#define H1 128
#define H2 64
#define ADJW (NN/32)   // 96 words per row

typedef unsigned int u32;
typedef unsigned short u16;

// ---------------- scratch (device globals; no allocation allowed) ----------------
__device__ unsigned g_adjbits[NN * ADJW];
__device__ float g_Whbuf[HEADS * NN * H1];
__device__ float g_src[HEADS * NN], g_dst[HEADS * NN];
__device__ float g_e1s[HEADS * NN], g_e2s[HEADS * NN];
__device__ float g_e1d[HEADS * NN], g_e2d[HEADS * NN];
__device__ unsigned g_maxenc[HEADS];
__device__ u16 g_WhH[HEADS * NN * H1];   // Wh hi bf16 bits (layer layout [h][n][f])
__device__ u16 g_WhL[HEADS * NN * H1];   // Wh lo bf16 bits
__device__ float g_hcat[NN * HEADS * H1];
__device__ float g_h1[NN * H1];

// ---------------- helpers ----------------
__device__ __forceinline__ unsigned enc_f(float v) {
    int b = __float_as_int(v);
    return b >= 0 ? ((unsigned)b | 0x80000000u) : (unsigned)(~b);
}
__device__ __forceinline__ float dec_f(unsigned e) {
    return (e & 0x80000000u) ? __uint_as_float(e & 0x7fffffffu)
                             : __uint_as_float(~e);
}
__device__ __forceinline__ u32 smem_u32(const void* p) {
    u32 a;
    asm("{ .reg .u64 t; cvta.to.shared.u64 t, %1; cvt.u32.u64 %0, t; }" : "=r"(a) : "l"(p));
    return a;
}
__device__ __forceinline__ void ldsm4(u32* r, u32 addr) {
    asm volatile("ldmatrix.sync.aligned.m8n8.x4.shared.b16 {%0,%1,%2,%3}, [%4];"
                 : "=r"(r[0]), "=r"(r[1]), "=r"(r[2]), "=r"(r[3]) : "r"(addr));
}
__device__ __forceinline__ void ldsm4t(u32* r, u32 addr) {
    asm volatile("ldmatrix.sync.aligned.m8n8.x4.trans.shared.b16 {%0,%1,%2,%3}, [%4];"
                 : "=r"(r[0]), "=r"(r[1]), "=r"(r[2]), "=r"(r[3]) : "r"(addr));
}
__device__ __forceinline__ void mma_bf16(float* d, const u32* a, const u32* b) {
    asm volatile(
        "mma.sync.aligned.m16n8k16.row.col.f32.bf16.bf16.f32 "
        "{%0,%1,%2,%3}, {%4,%5,%6,%7}, {%8,%9}, {%0,%1,%2,%3};"
        : "+f"(d[0]), "+f"(d[1]), "+f"(d[2]), "+f"(d[3])
        : "r"(a[0]), "r"(a[1]), "r"(a[2]), "r"(a[3]), "r"(b[0]), "r"(b[1]));
}

// ---------------- adjacency bit-pack ----------------
__global__ void pack_adj_k(const int* __restrict__ adj) {
    int idx = blockIdx.x * blockDim.x + threadIdx.x;
    int v = adj[idx] > 0;
    unsigned m = __ballot_sync(0xffffffffu, v);
    if ((idx & 31) == 0) g_adjbits[idx >> 5] = m;
}

// ---------------- per-head GEMM: Wh[h] = X @ W[h] ----------------
__global__ __launch_bounds__(256) void gemm_heads_k(
    const float* __restrict__ X, const float* __restrict__ W,
    float* __restrict__ out, int K, int F)
{
    int h = blockIdx.z;
    int m0 = blockIdx.x * 64, n0 = blockIdx.y * 64;
    const float* Wp = W + (size_t)h * K * F;
    float* Op = out + (size_t)h * NN * F;
    __shared__ float Xs[64][17];
    __shared__ __align__(16) float Ws[16][64];
    int tid = threadIdx.x, ty = tid / 16, tx = tid % 16;
    float acc[4][4] = {};
    for (int kt = 0; kt < K; kt += 16) {
        int r = tid >> 2, c = (tid & 3) * 4;
        float4 xv = *(const float4*)&X[(size_t)(m0 + r) * K + kt + c];
        Xs[r][c] = xv.x; Xs[r][c + 1] = xv.y; Xs[r][c + 2] = xv.z; Xs[r][c + 3] = xv.w;
        int r2 = tid >> 4, c2 = (tid & 15) * 4;
        *(float4*)&Ws[r2][c2] = *(const float4*)&Wp[(size_t)(kt + r2) * F + n0 + c2];
        __syncthreads();
#pragma unroll
        for (int k = 0; k < 16; k++) {
            float a[4], b[4];
#pragma unroll
            for (int i = 0; i < 4; i++) a[i] = Xs[ty * 4 + i][k];
#pragma unroll
            for (int j = 0; j < 4; j++) b[j] = Ws[k][tx * 4 + j];
#pragma unroll
            for (int i = 0; i < 4; i++)
#pragma unroll
                for (int j = 0; j < 4; j++) acc[i][j] = fmaf(a[i], b[j], acc[i][j]);
        }
        __syncthreads();
    }
#pragma unroll
    for (int i = 0; i < 4; i++) {
        float4 v = make_float4(acc[i][0], acc[i][1], acc[i][2], acc[i][3]);
        *(float4*)&Op[(size_t)(m0 + ty * 4 + i) * F + n0 + tx * 4] = v;
    }
}

// ---------------- src/dst projections + per-head max(dst) ----------------
__global__ void srcdst_k(const float* __restrict__ Wh, const float* __restrict__ as,
                         const float* __restrict__ ad, int F)
{
    int w = (blockIdx.x * blockDim.x + threadIdx.x) >> 5;
    int lane = threadIdx.x & 31;
    if (w >= HEADS * NN) return;
    int h = w / NN;
    const float* row = Wh + (size_t)w * F;
    float ss = 0.f, dd = 0.f;
    for (int f = lane; f < F; f += 32) {
        float v = row[f];
        ss = fmaf(v, as[h * F + f], ss);
        dd = fmaf(v, ad[h * F + f], dd);
    }
#pragma unroll
    for (int o = 16; o; o >>= 1) {
        ss += __shfl_xor_sync(0xffffffffu, ss, o);
        dd += __shfl_xor_sync(0xffffffffu, dd, o);
    }
    if (!lane) {
        g_src[w] = ss; g_dst[w] = dd;
        atomicMax(&g_maxenc[h], enc_f(dd));
    }
}

// ---------------- factored exps ----------------
__global__ void exps_k() {
    int i = blockIdx.x * blockDim.x + threadIdx.x;
    if (i >= HEADS * NN) return;
    int h = i / NN;
    float s = g_src[i], d = g_dst[i];
    float x = s + dec_f(g_maxenc[h]);
    float c = x > 0.f ? x : 0.2f * x;
    g_e1s[i] = expf(s - c);
    g_e2s[i] = expf(0.2f * s - c);
    g_e1d[i] = expf(d);
    g_e2d[i] = expf(0.2f * d);
}

// ---------------- elementwise bf16 hi/lo split of Wh ----------------
__global__ void split_k(const float* __restrict__ Wh, u16* __restrict__ hi,
                        u16* __restrict__ lo, int total)
{
    int i = blockIdx.x * blockDim.x + threadIdx.x;
    if (i >= total) return;
    float v = Wh[i];
    u32 u = __float_as_uint(v);
    hi[i] = (u16)(u >> 16);
    float rem = v - __uint_as_float(u & 0xffff0000u);
    lo[i] = (u16)(__float_as_uint(rem) >> 16);
}

// ---------------- HMMA attention: D = P @ Wh (bf16 3-term) ----------------
// grid (NN/128, HEADS), block 256 (8 warps: 4 m-groups x 2 n-groups)
template <int F>
__global__ __launch_bounds__(256) void attn_mma_k(
    const u16* __restrict__ WhH, const u16* __restrict__ WhL,
    float* __restrict__ hcat)
{
    constexpr int BK = 64;
    constexpr int NIT = NN / BK;
    constexpr int PST = BK + 8;            // P smem row stride (u16) = 72
    constexpr int BST = F + 8;             // B smem row stride (u16)
    constexpr int NW = F / 2;              // cols per n-group
    constexpr int NT = NW / 8;             // n-tiles per warp (8 or 4)
    constexpr int VPR = F / 8;             // uint4 per B row
    constexpr int SZ_P = 128 * PST * 2;    // bytes
    constexpr int SZ_B = BK * BST * 2;
    constexpr int OFF_PH = 0, OFF_PL = SZ_P;
    constexpr int OFF_BH = 2 * SZ_P, OFF_BL = 2 * SZ_P + SZ_B;
    constexpr int OFF_DJ = 2 * SZ_P + 2 * SZ_B;   // djd,dje1,dje2: 3*64 floats
    constexpr int OFF_RS = OFF_DJ + 3 * 64 * 4;   // rsum: 128 floats

    extern __shared__ char sm[];
    u32 smb = smem_u32(sm);
    u16* PsH = (u16*)(sm + OFF_PH);
    u16* PsL = (u16*)(sm + OFF_PL);
    float* djd  = (float*)(sm + OFF_DJ);
    float* dje1 = djd + 64;
    float* dje2 = djd + 128;
    float* rsum = (float*)(sm + OFF_RS);

    int tid = threadIdx.x, wid = tid >> 5, lane = tid & 31;
    int h = blockIdx.y, m0 = blockIdx.x * 128;
    int base = h * NN;
    const u16* WH = WhH + (size_t)base * F;
    const u16* WL = WhL + (size_t)base * F;

    // P-build role: 2 threads per row
    int rr = tid >> 1, half = tid & 1, kb = half * 32;
    float E1s = g_e1s[base + m0 + rr];
    float E2s = g_e2s[base + m0 + rr];
    float srcv = g_src[base + m0 + rr];
    float psum = 0.f;

    // mma role
    int wm = wid & 3, wn = wid >> 2;
    int mrow0 = wm * 32, nb0 = wn * NW;
    float acc[2][NT][4];
#pragma unroll
    for (int i = 0; i < 2; i++)
#pragma unroll
        for (int j = 0; j < NT; j++)
#pragma unroll
            for (int q = 0; q < 4; q++) acc[i][j][q] = 0.f;

    // ldmatrix source addresses (byte, smem window)
    u32 a_addr_h = smb + OFF_PH + ((mrow0 + (lane & 15)) * PST + (lane >> 4) * 8) * 2;
    u32 a_addr_l = a_addr_h + (OFF_PL - OFF_PH);
    u32 b_addr_h = smb + OFF_BH + ((lane & 15) * BST + nb0 + (lane >> 4) * 8) * 2;
    u32 b_addr_l = b_addr_h + (OFF_BL - OFF_BH);

    for (int it = 0; it < NIT; ++it) {
        int kt = it * BK;
        __syncthreads();   // previous tile's mma done
        // stage B tiles + dj arrays
        {
            const uint4* sh = (const uint4*)(WH + (size_t)kt * F);
            const uint4* sl = (const uint4*)(WL + (size_t)kt * F);
#pragma unroll
            for (int i = tid; i < BK * VPR; i += 256) {
                int row = i / VPR, c = (i % VPR) * 8;
                uint4 vh = sh[i], vl = sl[i];
                *(uint4*)(sm + OFF_BH + (row * BST + c) * 2) = vh;
                *(uint4*)(sm + OFF_BL + (row * BST + c) * 2) = vl;
            }
            if (tid < BK) {
                djd[tid]  = g_dst[base + kt + tid];
                dje1[tid] = g_e1d[base + kt + tid];
                dje2[tid] = g_e2d[base + kt + tid];
            }
        }
        __syncthreads();
        // build P tile (bf16 hi/lo, packed pairs)
        {
            unsigned word = g_adjbits[(size_t)(m0 + rr) * ADJW + (kt >> 5) + half];
#pragma unroll
            for (int c = 0; c < 16; c++) {
                int k0 = kb + 2 * c;
                float x0 = srcv + djd[k0];
                float p0 = (x0 > 0.f) ? E1s * dje1[k0] : E2s * dje2[k0];
                if (!((word >> (2 * c)) & 1u)) p0 = 0.f;
                float x1 = srcv + djd[k0 + 1];
                float p1 = (x1 > 0.f) ? E1s * dje1[k0 + 1] : E2s * dje2[k0 + 1];
                if (!((word >> (2 * c + 1)) & 1u)) p1 = 0.f;
                psum += p0 + p1;
                u32 u0 = __float_as_uint(p0), u1 = __float_as_uint(p1);
                u32 hip = (u0 >> 16) | (u1 & 0xffff0000u);
                float r0 = p0 - __uint_as_float(u0 & 0xffff0000u);
                float r1 = p1 - __uint_as_float(u1 & 0xffff0000u);
                u32 lop = (__float_as_uint(r0) >> 16) |
                          ((__float_as_uint(r1) >> 16) << 16);
                *(u32*)&PsH[rr * PST + k0] = hip;
                *(u32*)&PsL[rr * PST + k0] = lop;
            }
        }
        __syncthreads();
        // mma: acc += P(128x64) @ Wh(64xF), 3 split terms
#pragma unroll
        for (int ks = 0; ks < 4; ks++) {
            u32 ah[2][4], al[2][4];
#pragma unroll
            for (int mt = 0; mt < 2; mt++) {
                u32 off = (mt * 16 * PST + ks * 16) * 2;
                ldsm4(ah[mt], a_addr_h + off);
                ldsm4(al[mt], a_addr_l + off);
            }
#pragma unroll
            for (int ng = 0; ng < NT / 2; ng++) {
                u32 bh[4], bl[4];
                u32 off = (ks * 16 * BST + ng * 16) * 2;
                ldsm4t(bh, b_addr_h + off);
                ldsm4t(bl, b_addr_l + off);
#pragma unroll
                for (int mt = 0; mt < 2; mt++) {
                    mma_bf16(acc[mt][2 * ng],     ah[mt], bh);
                    mma_bf16(acc[mt][2 * ng + 1], ah[mt], bh + 2);
                    mma_bf16(acc[mt][2 * ng],     ah[mt], bl);
                    mma_bf16(acc[mt][2 * ng + 1], ah[mt], bl + 2);
                    mma_bf16(acc[mt][2 * ng],     al[mt], bh);
                    mma_bf16(acc[mt][2 * ng + 1], al[mt], bh + 2);
                }
            }
        }
    }

    // rowsums
    {
        float tot = psum + __shfl_xor_sync(0xffffffffu, psum, 1);
        if (!half) rsum[rr] = tot;
    }
    __syncthreads();

    // epilogue: normalize, elu, store
    constexpr int CAT = HEADS * F;
    int r0 = mrow0 + (lane >> 2);
    int c0 = nb0 + (lane & 3) * 2;
#pragma unroll
    for (int mt = 0; mt < 2; mt++) {
        int ra = r0 + mt * 16, rb = ra + 8;
        float inva = 1.f / rsum[ra];
        float invb = 1.f / rsum[rb];
        float* outa = &hcat[(size_t)(m0 + ra) * CAT + h * F];
        float* outb = &hcat[(size_t)(m0 + rb) * CAT + h * F];
#pragma unroll
        for (int nt = 0; nt < NT; nt++) {
            int cc = c0 + nt * 8;
            float v0 = acc[mt][nt][0] * inva; v0 = v0 > 0.f ? v0 : expm1f(v0);
            float v1 = acc[mt][nt][1] * inva; v1 = v1 > 0.f ? v1 : expm1f(v1);
            float v2 = acc[mt][nt][2] * invb; v2 = v2 > 0.f ? v2 : expm1f(v2);
            float v3 = acc[mt][nt][3] * invb; v3 = v3 > 0.f ? v3 : expm1f(v3);
            *(float2*)&outa[cc] = make_float2(v0, v1);
            *(float2*)&outb[cc] = make_float2(v2, v3);
        }
    }
}

// ---------------- combine: out = relu( elu(A@LIN) + B@RES ) ----------------
__global__ __launch_bounds__(256) void combine_k(
    const float* __restrict__ A, int KA, const float* __restrict__ LIN,
    const float* __restrict__ B, int KB, const float* __restrict__ RES,
    float* __restrict__ out, int FOUT)
{
    int m0 = blockIdx.x * 64, n0 = blockIdx.y * 64;
    __shared__ float Xs[64][17];
    __shared__ __align__(16) float Ws[16][64];
    int tid = threadIdx.x, ty = tid / 16, tx = tid % 16;
    float acc[4][4] = {};
    for (int kt = 0; kt < KA; kt += 16) {
        int r = tid >> 2, c = (tid & 3) * 4;
        float4 xv = *(const float4*)&A[(size_t)(m0 + r) * KA + kt + c];
        Xs[r][c] = xv.x; Xs[r][c + 1] = xv.y; Xs[r][c + 2] = xv.z; Xs[r][c + 3] = xv.w;
        int r2 = tid >> 4, c2 = (tid & 15) * 4;
        *(float4*)&Ws[r2][c2] = *(const float4*)&LIN[(size_t)(kt + r2) * FOUT + n0 + c2];
        __syncthreads();
#pragma unroll
        for (int k = 0; k < 16; k++) {
            float a[4], b[4];
#pragma unroll
            for (int i = 0; i < 4; i++) a[i] = Xs[ty * 4 + i][k];
#pragma unroll
            for (int j = 0; j < 4; j++) b[j] = Ws[k][tx * 4 + j];
#pragma unroll
            for (int i = 0; i < 4; i++)
#pragma unroll
                for (int j = 0; j < 4; j++) acc[i][j] = fmaf(a[i], b[j], acc[i][j]);
        }
        __syncthreads();
    }
#pragma unroll
    for (int i = 0; i < 4; i++)
#pragma unroll
        for (int j = 0; j < 4; j++)
            acc[i][j] = acc[i][j] > 0.f ? acc[i][j] : expm1f(acc[i][j]);
    for (int kt = 0; kt < KB; kt += 16) {
        int r = tid >> 2, c = (tid & 3) * 4;
        float4 xv = *(const float4*)&B[(size_t)(m0 + r) * KB + kt + c];
        Xs[r][c] = xv.x; Xs[r][c + 1] = xv.y; Xs[r][c + 2] = xv.z; Xs[r][c + 3] = xv.w;
        int r2 = tid >> 4, c2 = (tid & 15) * 4;
        *(float4*)&Ws[r2][c2] = *(const float4*)&RES[(size_t)(kt + r2) * FOUT + n0 + c2];
        __syncthreads();
#pragma unroll
        for (int k = 0; k < 16; k++) {
            float a[4], b[4];
#pragma unroll
            for (int i = 0; i < 4; i++) a[i] = Xs[ty * 4 + i][k];
#pragma unroll
            for (int j = 0; j < 4; j++) b[j] = Ws[k][tx * 4 + j];
#pragma unroll
            for (int i = 0; i < 4; i++)
#pragma unroll
                for (int j = 0; j < 4; j++) acc[i][j] = fmaf(a[i], b[j], acc[i][j]);
        }
        __syncthreads();
    }
#pragma unroll
    for (int i = 0; i < 4; i++) {
        float4 v;
        v.x = fmaxf(acc[i][0], 0.f); v.y = fmaxf(acc[i][1], 0.f);
        v.z = fmaxf(acc[i][2], 0.f); v.w = fmaxf(acc[i][3], 0.f);
        *(float4*)&out[(size_t)(m0 + ty * 4 + i) * FOUT + n0 + tx * 4] = v;
    }
}

// ---------------- host launcher ----------------
extern "C" void kernel_launch(void* const* d_in, const int* in_sizes, int n_in,
                              void* d_out, int out_size)
{
    const float* x    = (const float*)d_in[0];
    const int*   adj  = (const int*)d_in[1];
    const float* W1   = (const float*)d_in[2];
    const float* a1s  = (const float*)d_in[3];
    const float* a1d  = (const float*)d_in[4];
    const float* lin1 = (const float*)d_in[5];
    const float* res1 = (const float*)d_in[6];
    const float* W2   = (const float*)d_in[7];
    const float* a2s  = (const float*)d_in[8];
    const float* a2d  = (const float*)d_in[9];
    const float* lin2 = (const float*)d_in[10];
    const float* res2 = (const float*)d_in[11];
    float* out = (float*)d_out;

    float *whbuf, *hcat, *h1;
    u16 *whh, *whl;
    void* maxenc;
    cudaGetSymbolAddress((void**)&whbuf, g_Whbuf);
    cudaGetSymbolAddress((void**)&hcat,  g_hcat);
    cudaGetSymbolAddress((void**)&h1,    g_h1);
    cudaGetSymbolAddress((void**)&whh,   g_WhH);
    cudaGetSymbolAddress((void**)&whl,   g_WhL);
    cudaGetSymbolAddress(&maxenc, g_maxenc);

    // dynamic smem: 2*P + 2*B + dj(768) + rsum(512)
    constexpr int SM1 = 2 * (128 * 72 * 2) + 2 * (64 * 136 * 2) + 768 + 512; // 72,960
    constexpr int SM2 = 2 * (128 * 72 * 2) + 2 * (64 * 72 * 2)  + 768 + 512; // 56,576
    cudaFuncSetAttribute(attn_mma_k<H1>, cudaFuncAttributeMaxDynamicSharedMemorySize, SM1);
    cudaFuncSetAttribute(attn_mma_k<H2>, cudaFuncAttributeMaxDynamicSharedMemorySize, SM2);

    pack_adj_k<<<NN * NN / 256, 256>>>(adj);

    // ---- layer 1 ----
    cudaMemsetAsync(maxenc, 0, HEADS * sizeof(unsigned));
    gemm_heads_k<<<dim3(NN / 64, H1 / 64, HEADS), 256>>>(x, W1, whbuf, IN_DIM, H1);
    srcdst_k<<<HEADS * NN * 32 / 256, 256>>>(whbuf, a1s, a1d, H1);
    exps_k<<<(HEADS * NN + 255) / 256, 256>>>();
    split_k<<<(HEADS * NN * H1 + 255) / 256, 256>>>(whbuf, whh, whl, HEADS * NN * H1);
    attn_mma_k<H1><<<dim3(NN / 128, HEADS), 256, SM1>>>(whh, whl, hcat);
    combine_k<<<dim3(NN / 64, H1 / 64), 256>>>(hcat, HEADS * H1, lin1, x, IN_DIM, res1, h1, H1);

    // ---- layer 2 ----
    cudaMemsetAsync(maxenc, 0, HEADS * sizeof(unsigned));
    gemm_heads_k<<<dim3(NN / 64, H2 / 64, HEADS), 256>>>(h1, W2, whbuf, H1, H2);
    srcdst_k<<<HEADS * NN * 32 / 256, 256>>>(whbuf, a2s, a2d, H2);
    exps_k<<<(HEADS * NN + 255) / 256, 256>>>();
    split_k<<<(HEADS * NN * H2 + 255) / 256, 256>>>(whbuf, whh, whl, HEADS * NN * H2);
    attn_mma_k<H2><<<dim3(NN / 128, HEADS), 256, SM2>>>(whh, whl, hcat);
    combine_k<<<dim3(NN / 64, H2 / 64), 256>>>(hcat, HEADS * H2, lin2, h1, H1, res2, out, H2);
}

// round 5
// speedup vs baseline: 1.6516x; 1.1293x over previous
#include <cuda_runtime.h>
#include <math.h>
#include <cstdint>

#define NN 3072
#define HEADS 4
#define IN_DIM 256
#define H1 128
#define H2 64
#define ADJW (NN/32)

typedef unsigned int u32;
typedef unsigned short u16;

// ---------------- scratch ----------------
__device__ unsigned g_adjbits[NN * ADJW];
__device__ float g_Whbuf[HEADS * NN * H1];
__device__ float g_src[HEADS * NN], g_dst[HEADS * NN];
__device__ float g_e1s[HEADS * NN], g_e2s[HEADS * NN];
__device__ float g_e1d[HEADS * NN], g_e2d[HEADS * NN];
__device__ unsigned g_maxenc[HEADS];
__device__ u16 g_WhH[HEADS * NN * H1];
__device__ u16 g_WhL[HEADS * NN * H1];
__device__ float g_hcat[NN * HEADS * H1];
__device__ float g_h1[NN * H1];

// ---------------- helpers ----------------
__device__ __forceinline__ unsigned enc_f(float v) {
    int b = __float_as_int(v);
    return b >= 0 ? ((unsigned)b | 0x80000000u) : (unsigned)(~b);
}
__device__ __forceinline__ float dec_f(unsigned e) {
    return (e & 0x80000000u) ? __uint_as_float(e & 0x7fffffffu)
                             : __uint_as_float(~e);
}
__device__ __forceinline__ u32 smem_u32(const void* p) {
    u32 a;
    asm("{ .reg .u64 t; cvta.to.shared.u64 t, %1; cvt.u32.u64 %0, t; }" : "=r"(a) : "l"(p));
    return a;
}
__device__ __forceinline__ void ldsm4(u32* r, u32 addr) {
    asm volatile("ldmatrix.sync.aligned.m8n8.x4.shared.b16 {%0,%1,%2,%3}, [%4];"
                 : "=r"(r[0]), "=r"(r[1]), "=r"(r[2]), "=r"(r[3]) : "r"(addr));
}
__device__ __forceinline__ void ldsm4t(u32* r, u32 addr) {
    asm volatile("ldmatrix.sync.aligned.m8n8.x4.trans.shared.b16 {%0,%1,%2,%3}, [%4];"
                 : "=r"(r[0]), "=r"(r[1]), "=r"(r[2]), "=r"(r[3]) : "r"(addr));
}
__device__ __forceinline__ void mma_bf16(float* d, const u32* a, const u32* b) {
    asm volatile(
        "mma.sync.aligned.m16n8k16.row.col.f32.bf16.bf16.f32 "
        "{%0,%1,%2,%3}, {%4,%5,%6,%7}, {%8,%9}, {%0,%1,%2,%3};"
        : "+f"(d[0]), "+f"(d[1]), "+f"(d[2]), "+f"(d[3])
        : "r"(a[0]), "r"(a[1]), "r"(a[2]), "r"(a[3]), "r"(b[0]), "r"(b[1]));
}
#define CP_ASYNC16(dst, src) asm volatile("cp.async.cg.shared.global [%0], [%1], 16;" :: "r"(dst), "l"(src))
#define CP_COMMIT()  asm volatile("cp.async.commit_group;" ::: "memory")
#define CP_WAIT0()   asm volatile("cp.async.wait_group 0;" ::: "memory")

// ---------------- adjacency bit-pack ----------------
__global__ void pack_adj_k(const int* __restrict__ adj) {
    int idx = blockIdx.x * blockDim.x + threadIdx.x;
    int v = adj[idx] > 0;
    unsigned m = __ballot_sync(0xffffffffu, v);
    if ((idx & 31) == 0) g_adjbits[idx >> 5] = m;
}

// ---------------- per-head GEMM: Wh[h] = X @ W[h]  (+ fused bf16 split) ----------------
__global__ __launch_bounds__(256) void gemm_heads_k(
    const float* __restrict__ X, const float* __restrict__ W,
    float* __restrict__ out, u16* __restrict__ hi, u16* __restrict__ lo,
    int K, int F)
{
    int h = blockIdx.z;
    int m0 = blockIdx.x * 64, n0 = blockIdx.y * 64;
    const float* Wp = W + (size_t)h * K * F;
    size_t obase = (size_t)h * NN * F;
    __shared__ float Xs[64][17];
    __shared__ __align__(16) float Ws[16][64];
    int tid = threadIdx.x, ty = tid / 16, tx = tid % 16;
    float acc[4][4] = {};
    for (int kt = 0; kt < K; kt += 16) {
        int r = tid >> 2, c = (tid & 3) * 4;
        float4 xv = *(const float4*)&X[(size_t)(m0 + r) * K + kt + c];
        Xs[r][c] = xv.x; Xs[r][c + 1] = xv.y; Xs[r][c + 2] = xv.z; Xs[r][c + 3] = xv.w;
        int r2 = tid >> 4, c2 = (tid & 15) * 4;
        *(float4*)&Ws[r2][c2] = *(const float4*)&Wp[(size_t)(kt + r2) * F + n0 + c2];
        __syncthreads();
#pragma unroll
        for (int k = 0; k < 16; k++) {
            float a[4], b[4];
#pragma unroll
            for (int i = 0; i < 4; i++) a[i] = Xs[ty * 4 + i][k];
#pragma unroll
            for (int j = 0; j < 4; j++) b[j] = Ws[k][tx * 4 + j];
#pragma unroll
            for (int i = 0; i < 4; i++)
#pragma unroll
                for (int j = 0; j < 4; j++) acc[i][j] = fmaf(a[i], b[j], acc[i][j]);
        }
        __syncthreads();
    }
#pragma unroll
    for (int i = 0; i < 4; i++) {
        size_t o = obase + (size_t)(m0 + ty * 4 + i) * F + n0 + tx * 4;
        float4 v = make_float4(acc[i][0], acc[i][1], acc[i][2], acc[i][3]);
        *(float4*)&out[o] = v;
        ushort4 vh, vl;
        u32 u;
        u = __float_as_uint(acc[i][0]); vh.x = (u16)(u >> 16);
        vl.x = (u16)(__float_as_uint(acc[i][0] - __uint_as_float(u & 0xffff0000u)) >> 16);
        u = __float_as_uint(acc[i][1]); vh.y = (u16)(u >> 16);
        vl.y = (u16)(__float_as_uint(acc[i][1] - __uint_as_float(u & 0xffff0000u)) >> 16);
        u = __float_as_uint(acc[i][2]); vh.z = (u16)(u >> 16);
        vl.z = (u16)(__float_as_uint(acc[i][2] - __uint_as_float(u & 0xffff0000u)) >> 16);
        u = __float_as_uint(acc[i][3]); vh.w = (u16)(u >> 16);
        vl.w = (u16)(__float_as_uint(acc[i][3] - __uint_as_float(u & 0xffff0000u)) >> 16);
        *(ushort4*)&hi[o] = vh;
        *(ushort4*)&lo[o] = vl;
    }
}

// ---------------- src/dst projections + per-head max(dst) ----------------
__global__ void srcdst_k(const float* __restrict__ Wh, const float* __restrict__ as,
                         const float* __restrict__ ad, int F)
{
    int w = (blockIdx.x * blockDim.x + threadIdx.x) >> 5;
    int lane = threadIdx.x & 31;
    if (w >= HEADS * NN) return;
    int h = w / NN;
    const float* row = Wh + (size_t)w * F;
    float ss = 0.f, dd = 0.f;
    for (int f = lane; f < F; f += 32) {
        float v = row[f];
        ss = fmaf(v, as[h * F + f], ss);
        dd = fmaf(v, ad[h * F + f], dd);
    }
#pragma unroll
    for (int o = 16; o; o >>= 1) {
        ss += __shfl_xor_sync(0xffffffffu, ss, o);
        dd += __shfl_xor_sync(0xffffffffu, dd, o);
    }
    if (!lane) {
        g_src[w] = ss; g_dst[w] = dd;
        atomicMax(&g_maxenc[h], enc_f(dd));
    }
}

// ---------------- factored exps ----------------
__global__ void exps_k() {
    int i = blockIdx.x * blockDim.x + threadIdx.x;
    if (i >= HEADS * NN) return;
    int h = i / NN;
    float s = g_src[i], d = g_dst[i];
    float x = s + dec_f(g_maxenc[h]);
    float c = x > 0.f ? x : 0.2f * x;
    g_e1s[i] = expf(s - c);
    g_e2s[i] = expf(0.2f * s - c);
    g_e1d[i] = expf(d);
    g_e2d[i] = expf(0.2f * d);
}

// ---------------- HMMA attention: D = P @ Wh (bf16 3-term, pipelined) ----------------
// grid (NN/128, HEADS), block 256 (8 warps: 4 m-groups x 2 n-groups)
template <int F>
__global__ __launch_bounds__(256) void attn_mma_k(
    const u16* __restrict__ WhH, const u16* __restrict__ WhL,
    float* __restrict__ hcat)
{
    constexpr int BK = 64;
    constexpr int NIT = NN / BK;
    constexpr int PST = BK + 8;           // 72
    constexpr int BST = F + 8;
    constexpr int NW = F / 2;
    constexpr int NT = NW / 8;            // 8 (F=128) / 4 (F=64)
    constexpr int NG = NT / 2;            // 4 / 2
    constexpr int VPR = F / 8;
    constexpr int SZ_P = 128 * PST * 2;
    constexpr int SZ_B = BK * BST * 2;
    constexpr int OFF_P = 0;              // [s*2+part]*SZ_P : parts hi,lo
    constexpr int OFF_B = 4 * SZ_P;
    constexpr int OFF_DJ = OFF_B + 4 * SZ_B;   // [s][3][64] floats
    constexpr int OFF_RS = OFF_DJ + 2 * 768;

    extern __shared__ char sm[];
    u32 smb = smem_u32(sm);
    float* rsum = (float*)(sm + OFF_RS);

    int tid = threadIdx.x, wid = tid >> 5, lane = tid & 31;
    int h = blockIdx.y, m0 = blockIdx.x * 128;
    int base = h * NN;
    const u16* WH = WhH + (size_t)base * F;
    const u16* WL = WhL + (size_t)base * F;

    // P-build role
    int rr = tid >> 1, half = tid & 1, kb = half * 32;
    float E1s = g_e1s[base + m0 + rr];
    float E2s = g_e2s[base + m0 + rr];
    float srcv = g_src[base + m0 + rr];
    float psum = 0.f;
    u32 adjrow_base = (u32)((m0 + rr) * ADJW) + half;

    // mma role
    int wm = wid & 3, wn = wid >> 2;
    int mrow0 = wm * 32, nb0 = wn * NW;
    float acc[2][NT][4];
#pragma unroll
    for (int i = 0; i < 2; i++)
#pragma unroll
        for (int j = 0; j < NT; j++)
#pragma unroll
            for (int q = 0; q < 4; q++) acc[i][j][q] = 0.f;

    // ldmatrix base addresses per stage
    u32 aoff = (u32)(((mrow0 + (lane & 15)) * PST + (lane >> 4) * 8) * 2);
    u32 boff = (u32)((((lane & 15)) * BST + nb0 + (lane >> 4) * 8) * 2);

    // ---- staging helper (cp.async) ----
    auto stage = [&](int s, int kt) {
        u32 bhb = smb + OFF_B + (s * 2 + 0) * SZ_B;
        u32 blb = smb + OFF_B + (s * 2 + 1) * SZ_B;
        const uint4* sh = (const uint4*)(WH + (size_t)kt * F);
        const uint4* sl = (const uint4*)(WL + (size_t)kt * F);
#pragma unroll
        for (int i = tid; i < BK * VPR; i += 256) {
            int row = i / VPR, c = (i % VPR) * 8;
            u32 d = (u32)((row * BST + c) * 2);
            CP_ASYNC16(bhb + d, sh + i);
            CP_ASYNC16(blb + d, sl + i);
        }
        if (tid < 48) {
            int which = tid >> 4, q = tid & 15;
            const float* src = (which == 0 ? g_dst : which == 1 ? g_e1d : g_e2d)
                               + base + kt + q * 4;
            CP_ASYNC16(smb + OFF_DJ + s * 768 + which * 256 + q * 16, src);
        }
        CP_COMMIT();
    };

    // ---- P-build helper ----
    auto buildP = [&](int s, int kt) {
        float* djd  = (float*)(sm + OFF_DJ + s * 768);
        float* dje1 = djd + 64;
        float* dje2 = djd + 128;
        u16* PsH = (u16*)(sm + OFF_P + (s * 2 + 0) * SZ_P);
        u16* PsL = (u16*)(sm + OFF_P + (s * 2 + 1) * SZ_P);
        unsigned word = g_adjbits[adjrow_base + (kt >> 5)];
#pragma unroll
        for (int c = 0; c < 16; c++) {
            int k0 = kb + 2 * c;
            float2 dd = *(float2*)&djd[k0];
            float2 e1 = *(float2*)&dje1[k0];
            float2 e2 = *(float2*)&dje2[k0];
            float x0 = srcv + dd.x;
            float p0 = (x0 > 0.f) ? E1s * e1.x : E2s * e2.x;
            if (!((word >> (2 * c)) & 1u)) p0 = 0.f;
            float x1 = srcv + dd.y;
            float p1 = (x1 > 0.f) ? E1s * e1.y : E2s * e2.y;
            if (!((word >> (2 * c + 1)) & 1u)) p1 = 0.f;
            psum += p0 + p1;
            u32 u0 = __float_as_uint(p0), u1 = __float_as_uint(p1);
            u32 hip = (u0 >> 16) | (u1 & 0xffff0000u);
            float r0 = p0 - __uint_as_float(u0 & 0xffff0000u);
            float r1 = p1 - __uint_as_float(u1 & 0xffff0000u);
            u32 lop = (__float_as_uint(r0) >> 16) |
                      ((__float_as_uint(r1) >> 16) << 16);
            *(u32*)&PsH[rr * PST + k0] = hip;
            *(u32*)&PsL[rr * PST + k0] = lop;
        }
    };

    // ---- mma helper (acc-distance-optimized) ----
    auto do_mma = [&](int s) {
        u32 aH = smb + OFF_P + (s * 2 + 0) * SZ_P + aoff;
        u32 aL = smb + OFF_P + (s * 2 + 1) * SZ_P + aoff;
        u32 bH = smb + OFF_B + (s * 2 + 0) * SZ_B + boff;
        u32 bL = smb + OFF_B + (s * 2 + 1) * SZ_B + boff;
#pragma unroll
        for (int ks = 0; ks < 4; ks++) {
            u32 ah[2][4], al[2][4];
#pragma unroll
            for (int mt = 0; mt < 2; mt++) {
                u32 off = (u32)((mt * 16 * PST + ks * 16) * 2);
                ldsm4(ah[mt], aH + off);
                ldsm4(al[mt], aL + off);
            }
            u32 bh[NG][4], bl[NG][4];
#pragma unroll
            for (int ng = 0; ng < NG; ng++) {
                u32 off = (u32)((ks * 16 * BST + ng * 16) * 2);
                ldsm4t(bh[ng], bH + off);
                ldsm4t(bl[ng], bL + off);
            }
            // pass 1: hi*hi  (all distinct accs)
#pragma unroll
            for (int ng = 0; ng < NG; ng++)
#pragma unroll
                for (int mt = 0; mt < 2; mt++) {
                    mma_bf16(acc[mt][2 * ng],     ah[mt], bh[ng]);
                    mma_bf16(acc[mt][2 * ng + 1], ah[mt], bh[ng] + 2);
                }
            // pass 2: hi*lo
#pragma unroll
            for (int ng = 0; ng < NG; ng++)
#pragma unroll
                for (int mt = 0; mt < 2; mt++) {
                    mma_bf16(acc[mt][2 * ng],     ah[mt], bl[ng]);
                    mma_bf16(acc[mt][2 * ng + 1], ah[mt], bl[ng] + 2);
                }
            // pass 3: lo*hi
#pragma unroll
            for (int ng = 0; ng < NG; ng++)
#pragma unroll
                for (int mt = 0; mt < 2; mt++) {
                    mma_bf16(acc[mt][2 * ng],     al[mt], bh[ng]);
                    mma_bf16(acc[mt][2 * ng + 1], al[mt], bh[ng] + 2);
                }
        }
    };

    // ---- prologue: stage tile 0, build P0 ----
    stage(0, 0);
    CP_WAIT0();
    __syncthreads();
    buildP(0, 0);
    __syncthreads();

    // ---- pipelined mainloop ----
    for (int it = 0; it < NIT; ++it) {
        int s = it & 1;
        if (it + 1 < NIT) stage((it + 1) & 1, (it + 1) * BK);
        do_mma(s);
        if (it + 1 < NIT) {
            CP_WAIT0();
            buildP((it + 1) & 1, (it + 1) * BK);
        }
        __syncthreads();
    }

    // rowsums
    {
        float tot = psum + __shfl_xor_sync(0xffffffffu, psum, 1);
        if (!half) rsum[rr] = tot;
    }
    __syncthreads();

    // epilogue
    constexpr int CAT = HEADS * F;
    int r0 = mrow0 + (lane >> 2);
    int c0 = nb0 + (lane & 3) * 2;
#pragma unroll
    for (int mt = 0; mt < 2; mt++) {
        int ra = r0 + mt * 16, rb = ra + 8;
        float inva = 1.f / rsum[ra];
        float invb = 1.f / rsum[rb];
        float* outa = &hcat[(size_t)(m0 + ra) * CAT + h * F];
        float* outb = &hcat[(size_t)(m0 + rb) * CAT + h * F];
#pragma unroll
        for (int nt = 0; nt < NT; nt++) {
            int cc = c0 + nt * 8;
            float v0 = acc[mt][nt][0] * inva; v0 = v0 > 0.f ? v0 : expm1f(v0);
            float v1 = acc[mt][nt][1] * inva; v1 = v1 > 0.f ? v1 : expm1f(v1);
            float v2 = acc[mt][nt][2] * invb; v2 = v2 > 0.f ? v2 : expm1f(v2);
            float v3 = acc[mt][nt][3] * invb; v3 = v3 > 0.f ? v3 : expm1f(v3);
            *(float2*)&outa[cc] = make_float2(v0, v1);
            *(float2*)&outb[cc] = make_float2(v2, v3);
        }
    }
}

// ---------------- combine: out = relu( elu(A@LIN) + B@RES ) ----------------
__global__ __launch_bounds__(256) void combine_k(
    const float* __restrict__ A, int KA, const float* __restrict__ LIN,
    const float* __restrict__ B, int KB, const float* __restrict__ RES,
    float* __restrict__ out, int FOUT)
{
    int m0 = blockIdx.x * 64, n0 = blockIdx.y * 64;
    __shared__ float Xs[64][17];
    __shared__ __align__(16) float Ws[16][64];
    int tid = threadIdx.x, ty = tid / 16, tx = tid % 16;
    float acc[4][4] = {};
    for (int kt = 0; kt < KA; kt += 16) {
        int r = tid >> 2, c = (tid & 3) * 4;
        float4 xv = *(const float4*)&A[(size_t)(m0 + r) * KA + kt + c];
        Xs[r][c] = xv.x; Xs[r][c + 1] = xv.y; Xs[r][c + 2] = xv.z; Xs[r][c + 3] = xv.w;
        int r2 = tid >> 4, c2 = (tid & 15) * 4;
        *(float4*)&Ws[r2][c2] = *(const float4*)&LIN[(size_t)(kt + r2) * FOUT + n0 + c2];
        __syncthreads();
#pragma unroll
        for (int k = 0; k < 16; k++) {
            float a[4], b[4];
#pragma unroll
            for (int i = 0; i < 4; i++) a[i] = Xs[ty * 4 + i][k];
#pragma unroll
            for (int j = 0; j < 4; j++) b[j] = Ws[k][tx * 4 + j];
#pragma unroll
            for (int i = 0; i < 4; i++)
#pragma unroll
                for (int j = 0; j < 4; j++) acc[i][j] = fmaf(a[i], b[j], acc[i][j]);
        }
        __syncthreads();
    }
#pragma unroll
    for (int i = 0; i < 4; i++)
#pragma unroll
        for (int j = 0; j < 4; j++)
            acc[i][j] = acc[i][j] > 0.f ? acc[i][j] : expm1f(acc[i][j]);
    for (int kt = 0; kt < KB; kt += 16) {
        int r = tid >> 2, c = (tid & 3) * 4;
        float4 xv = *(const float4*)&B[(size_t)(m0 + r) * KB + kt + c];
        Xs[r][c] = xv.x; Xs[r][c + 1] = xv.y; Xs[r][c + 2] = xv.z; Xs[r][c + 3] = xv.w;
        int r2 = tid >> 4, c2 = (tid & 15) * 4;
        *(float4*)&Ws[r2][c2] = *(const float4*)&RES[(size_t)(kt + r2) * FOUT + n0 + c2];
        __syncthreads();
#pragma unroll
        for (int k = 0; k < 16; k++) {
            float a[4], b[4];
#pragma unroll
            for (int i = 0; i < 4; i++) a[i] = Xs[ty * 4 + i][k];
#pragma unroll
            for (int j = 0; j < 4; j++) b[j] = Ws[k][tx * 4 + j];
#pragma unroll
            for (int i = 0; i < 4; i++)
#pragma unroll
                for (int j = 0; j < 4; j++) acc[i][j] = fmaf(a[i], b[j], acc[i][j]);
        }
        __syncthreads();
    }
#pragma unroll
    for (int i = 0; i < 4; i++) {
        float4 v;
        v.x = fmaxf(acc[i][0], 0.f); v.y = fmaxf(acc[i][1], 0.f);
        v.z = fmaxf(acc[i][2], 0.f); v.w = fmaxf(acc[i][3], 0.f);
        *(float4*)&out[(size_t)(m0 + ty * 4 + i) * FOUT + n0 + tx * 4] = v;
    }
}

// ---------------- host launcher ----------------
extern "C" void kernel_launch(void* const* d_in, const int* in_sizes, int n_in,
                              void* d_out, int out_size)
{
    const float* x    = (const float*)d_in[0];
    const int*   adj  = (const int*)d_in[1];
    const float* W1   = (const float*)d_in[2];
    const float* a1s  = (const float*)d_in[3];
    const float* a1d  = (const float*)d_in[4];
    const float* lin1 = (const float*)d_in[5];
    const float* res1 = (const float*)d_in[6];
    const float* W2   = (const float*)d_in[7];
    const float* a2s  = (const float*)d_in[8];
    const float* a2d  = (const float*)d_in[9];
    const float* lin2 = (const float*)d_in[10];
    const float* res2 = (const float*)d_in[11];
    float* out = (float*)d_out;

    float *whbuf, *hcat, *h1;
    u16 *whh, *whl;
    void* maxenc;
    cudaGetSymbolAddress((void**)&whbuf, g_Whbuf);
    cudaGetSymbolAddress((void**)&hcat,  g_hcat);
    cudaGetSymbolAddress((void**)&h1,    g_h1);
    cudaGetSymbolAddress((void**)&whh,   g_WhH);
    cudaGetSymbolAddress((void**)&whl,   g_WhL);
    cudaGetSymbolAddress(&maxenc, g_maxenc);

    // smem: 4*SZ_P + 4*SZ_B + 2*768 + rsum(512)
    constexpr int SZP = 128 * 72 * 2;
    constexpr int SM1 = 4 * SZP + 4 * (64 * 136 * 2) + 2 * 768 + 512; // 145,408
    constexpr int SM2 = 4 * SZP + 4 * (64 * 72 * 2)  + 2 * 768 + 512; // 112,640
    cudaFuncSetAttribute(attn_mma_k<H1>, cudaFuncAttributeMaxDynamicSharedMemorySize, SM1);
    cudaFuncSetAttribute(attn_mma_k<H2>, cudaFuncAttributeMaxDynamicSharedMemorySize, SM2);

    pack_adj_k<<<NN * NN / 256, 256>>>(adj);

    // ---- layer 1 ----
    cudaMemsetAsync(maxenc, 0, HEADS * sizeof(unsigned));
    gemm_heads_k<<<dim3(NN / 64, H1 / 64, HEADS), 256>>>(x, W1, whbuf, whh, whl, IN_DIM, H1);
    srcdst_k<<<HEADS * NN * 32 / 256, 256>>>(whbuf, a1s, a1d, H1);
    exps_k<<<(HEADS * NN + 255) / 256, 256>>>();
    attn_mma_k<H1><<<dim3(NN / 128, HEADS), 256, SM1>>>(whh, whl, hcat);
    combine_k<<<dim3(NN / 64, H1 / 64), 256>>>(hcat, HEADS * H1, lin1, x, IN_DIM, res1, h1, H1);

    // ---- layer 2 ----
    cudaMemsetAsync(maxenc, 0, HEADS * sizeof(unsigned));
    gemm_heads_k<<<dim3(NN / 64, H2 / 64, HEADS), 256>>>(h1, W2, whbuf, whh, whl, H1, H2);
    srcdst_k<<<HEADS * NN * 32 / 256, 256>>>(whbuf, a2s, a2d, H2);
    exps_k<<<(HEADS * NN + 255) / 256, 256>>>();
    attn_mma_k<H2><<<dim3(NN / 128, HEADS), 256, SM2>>>(whh, whl, hcat);
    combine_k<<<dim3(NN / 64, H2 / 64), 256>>>(hcat, HEADS * H2, lin2, h1, H1, res2, out, H2);
}

// round 6
// speedup vs baseline: 1.9189x; 1.1618x over previous
#include <cuda_runtime.h>
#include <cuda_fp16.h>
#include <math.h>
#include <cstdint>

#define NN 3072
#define HEADS 4
#define IN_DIM 256
#define H1 128
#define H2 64
#define ADJW (NN/32)

typedef unsigned int u32;
typedef unsigned short u16;

// ---------------- scratch ----------------
__device__ unsigned g_adjbits[NN * ADJW];
__device__ float g_Whbuf[HEADS * NN * H1];
__device__ float g_src[HEADS * NN], g_dst[HEADS * NN];
__device__ float g_e1s[HEADS * NN], g_e2s[HEADS * NN];
__device__ float g_e1d[HEADS * NN], g_e2d[HEADS * NN];
__device__ unsigned g_maxenc[HEADS];
__device__ u16 g_WhH[HEADS * NN * H1];   // Wh hi fp16
__device__ u16 g_WhL[HEADS * NN * H1];   // Wh lo fp16 (residual)
__device__ float g_hcat[NN * HEADS * H1];
__device__ float g_h1[NN * H1];

// ---------------- helpers ----------------
__device__ __forceinline__ unsigned enc_f(float v) {
    int b = __float_as_int(v);
    return b >= 0 ? ((unsigned)b | 0x80000000u) : (unsigned)(~b);
}
__device__ __forceinline__ float dec_f(unsigned e) {
    return (e & 0x80000000u) ? __uint_as_float(e & 0x7fffffffu)
                             : __uint_as_float(~e);
}
__device__ __forceinline__ u32 smem_u32(const void* p) {
    u32 a;
    asm("{ .reg .u64 t; cvta.to.shared.u64 t, %1; cvt.u32.u64 %0, t; }" : "=r"(a) : "l"(p));
    return a;
}
__device__ __forceinline__ void ldsm4(u32* r, u32 addr) {
    asm volatile("ldmatrix.sync.aligned.m8n8.x4.shared.b16 {%0,%1,%2,%3}, [%4];"
                 : "=r"(r[0]), "=r"(r[1]), "=r"(r[2]), "=r"(r[3]) : "r"(addr));
}
__device__ __forceinline__ void ldsm4t(u32* r, u32 addr) {
    asm volatile("ldmatrix.sync.aligned.m8n8.x4.trans.shared.b16 {%0,%1,%2,%3}, [%4];"
                 : "=r"(r[0]), "=r"(r[1]), "=r"(r[2]), "=r"(r[3]) : "r"(addr));
}
__device__ __forceinline__ void mma_f16(float* d, const u32* a, const u32* b) {
    asm volatile(
        "mma.sync.aligned.m16n8k16.row.col.f32.f16.f16.f32 "
        "{%0,%1,%2,%3}, {%4,%5,%6,%7}, {%8,%9}, {%0,%1,%2,%3};"
        : "+f"(d[0]), "+f"(d[1]), "+f"(d[2]), "+f"(d[3])
        : "r"(a[0]), "r"(a[1]), "r"(a[2]), "r"(a[3]), "r"(b[0]), "r"(b[1]));
}
#define CP_ASYNC16(dst, src) asm volatile("cp.async.cg.shared.global [%0], [%1], 16;" :: "r"(dst), "l"(src))
#define CP_COMMIT()  asm volatile("cp.async.commit_group;" ::: "memory")
#define CP_WAIT0()   asm volatile("cp.async.wait_group 0;" ::: "memory")

// ---------------- adjacency bit-pack ----------------
__global__ void pack_adj_k(const int* __restrict__ adj) {
    int idx = blockIdx.x * blockDim.x + threadIdx.x;
    int v = adj[idx] > 0;
    unsigned m = __ballot_sync(0xffffffffu, v);
    if ((idx & 31) == 0) g_adjbits[idx >> 5] = m;
}

// ---------------- per-head GEMM: Wh[h] = X @ W[h]  (+ fused fp16 split) ----------------
__global__ __launch_bounds__(256) void gemm_heads_k(
    const float* __restrict__ X, const float* __restrict__ W,
    float* __restrict__ out, u16* __restrict__ hi, u16* __restrict__ lo,
    int K, int F)
{
    int h = blockIdx.z;
    int m0 = blockIdx.x * 64, n0 = blockIdx.y * 64;
    const float* Wp = W + (size_t)h * K * F;
    size_t obase = (size_t)h * NN * F;
    __shared__ float Xs[64][17];
    __shared__ __align__(16) float Ws[16][64];
    int tid = threadIdx.x, ty = tid / 16, tx = tid % 16;
    float acc[4][4] = {};
    for (int kt = 0; kt < K; kt += 16) {
        int r = tid >> 2, c = (tid & 3) * 4;
        float4 xv = *(const float4*)&X[(size_t)(m0 + r) * K + kt + c];
        Xs[r][c] = xv.x; Xs[r][c + 1] = xv.y; Xs[r][c + 2] = xv.z; Xs[r][c + 3] = xv.w;
        int r2 = tid >> 4, c2 = (tid & 15) * 4;
        *(float4*)&Ws[r2][c2] = *(const float4*)&Wp[(size_t)(kt + r2) * F + n0 + c2];
        __syncthreads();
#pragma unroll
        for (int k = 0; k < 16; k++) {
            float a[4], b[4];
#pragma unroll
            for (int i = 0; i < 4; i++) a[i] = Xs[ty * 4 + i][k];
#pragma unroll
            for (int j = 0; j < 4; j++) b[j] = Ws[k][tx * 4 + j];
#pragma unroll
            for (int i = 0; i < 4; i++)
#pragma unroll
                for (int j = 0; j < 4; j++) acc[i][j] = fmaf(a[i], b[j], acc[i][j]);
        }
        __syncthreads();
    }
#pragma unroll
    for (int i = 0; i < 4; i++) {
        size_t o = obase + (size_t)(m0 + ty * 4 + i) * F + n0 + tx * 4;
        *(float4*)&out[o] = make_float4(acc[i][0], acc[i][1], acc[i][2], acc[i][3]);
        ushort4 vh, vl;
        __half t;
        t = __float2half_rn(acc[i][0]); vh.x = __half_as_ushort(t);
        vl.x = __half_as_ushort(__float2half_rn(acc[i][0] - __half2float(t)));
        t = __float2half_rn(acc[i][1]); vh.y = __half_as_ushort(t);
        vl.y = __half_as_ushort(__float2half_rn(acc[i][1] - __half2float(t)));
        t = __float2half_rn(acc[i][2]); vh.z = __half_as_ushort(t);
        vl.z = __half_as_ushort(__float2half_rn(acc[i][2] - __half2float(t)));
        t = __float2half_rn(acc[i][3]); vh.w = __half_as_ushort(t);
        vl.w = __half_as_ushort(__float2half_rn(acc[i][3] - __half2float(t)));
        *(ushort4*)&hi[o] = vh;
        *(ushort4*)&lo[o] = vl;
    }
}

// ---------------- src/dst projections + per-head max(dst) ----------------
__global__ void srcdst_k(const float* __restrict__ Wh, const float* __restrict__ as,
                         const float* __restrict__ ad, int F)
{
    int w = (blockIdx.x * blockDim.x + threadIdx.x) >> 5;
    int lane = threadIdx.x & 31;
    if (w >= HEADS * NN) return;
    int h = w / NN;
    const float* row = Wh + (size_t)w * F;
    float ss = 0.f, dd = 0.f;
    for (int f = lane; f < F; f += 32) {
        float v = row[f];
        ss = fmaf(v, as[h * F + f], ss);
        dd = fmaf(v, ad[h * F + f], dd);
    }
#pragma unroll
    for (int o = 16; o; o >>= 1) {
        ss += __shfl_xor_sync(0xffffffffu, ss, o);
        dd += __shfl_xor_sync(0xffffffffu, dd, o);
    }
    if (!lane) {
        g_src[w] = ss; g_dst[w] = dd;
        atomicMax(&g_maxenc[h], enc_f(dd));
    }
}

// ---------------- factored exps ----------------
__global__ void exps_k() {
    int i = blockIdx.x * blockDim.x + threadIdx.x;
    if (i >= HEADS * NN) return;
    int h = i / NN;
    float s = g_src[i], d = g_dst[i];
    float x = s + dec_f(g_maxenc[h]);
    float c = x > 0.f ? x : 0.2f * x;
    g_e1s[i] = expf(s - c);
    g_e2s[i] = expf(0.2f * s - c);
    g_e1d[i] = expf(d);
    g_e2d[i] = expf(0.2f * d);
}

// ---------------- HMMA attention: D = P @ Wh (fp16, 2-term) ----------------
// grid (NN/128, HEADS), block 256 (8 warps: 4 m-groups x 2 n-groups)
template <int F>
__global__ __launch_bounds__(256) void attn_mma_k(
    const u16* __restrict__ WhH, const u16* __restrict__ WhL,
    float* __restrict__ hcat)
{
    constexpr int BK = 64;
    constexpr int NIT = NN / BK;
    constexpr int PST = BK + 8;           // 72 halves
    constexpr int BST = F + 8;
    constexpr int NW = F / 2;
    constexpr int NT = NW / 8;            // 8 (F=128) / 4 (F=64)
    constexpr int NG = NT / 2;
    constexpr int VPR = F / 8;
    constexpr int SZ_P = 128 * PST * 2;   // single fp16 P per stage
    constexpr int SZ_B = BK * BST * 2;
    constexpr int OFF_P = 0;              // [s]*SZ_P
    constexpr int OFF_B = 2 * SZ_P;       // [s*2+part]*SZ_B
    constexpr int OFF_DJ = OFF_B + 4 * SZ_B;
    constexpr int OFF_RS = OFF_DJ + 2 * 768;

    extern __shared__ char sm[];
    u32 smb = smem_u32(sm);
    float* rsum = (float*)(sm + OFF_RS);

    int tid = threadIdx.x, wid = tid >> 5, lane = tid & 31;
    int h = blockIdx.y, m0 = blockIdx.x * 128;
    int base = h * NN;
    const u16* WH = WhH + (size_t)base * F;
    const u16* WL = WhL + (size_t)base * F;

    // P-build role
    int rr = tid >> 1, half = tid & 1, kb = half * 32;
    float E1s = g_e1s[base + m0 + rr];
    float E2s = g_e2s[base + m0 + rr];
    float srcv = g_src[base + m0 + rr];
    float psum = 0.f;
    u32 adjrow_base = (u32)((m0 + rr) * ADJW) + half;

    // mma role
    int wm = wid & 3, wn = wid >> 2;
    int mrow0 = wm * 32, nb0 = wn * NW;
    float acc[2][NT][4];
#pragma unroll
    for (int i = 0; i < 2; i++)
#pragma unroll
        for (int j = 0; j < NT; j++)
#pragma unroll
            for (int q = 0; q < 4; q++) acc[i][j][q] = 0.f;

    u32 aoff = (u32)(((mrow0 + (lane & 15)) * PST + (lane >> 4) * 8) * 2);
    u32 boff = (u32)((((lane & 15)) * BST + nb0 + (lane >> 4) * 8) * 2);

    auto stage = [&](int s, int kt) {
        u32 bhb = smb + OFF_B + (s * 2 + 0) * SZ_B;
        u32 blb = smb + OFF_B + (s * 2 + 1) * SZ_B;
        const uint4* sh = (const uint4*)(WH + (size_t)kt * F);
        const uint4* sl = (const uint4*)(WL + (size_t)kt * F);
#pragma unroll
        for (int i = tid; i < BK * VPR; i += 256) {
            int row = i / VPR, c = (i % VPR) * 8;
            u32 d = (u32)((row * BST + c) * 2);
            CP_ASYNC16(bhb + d, sh + i);
            CP_ASYNC16(blb + d, sl + i);
        }
        if (tid < 48) {
            int which = tid >> 4, q = tid & 15;
            const float* src = (which == 0 ? g_dst : which == 1 ? g_e1d : g_e2d)
                               + base + kt + q * 4;
            CP_ASYNC16(smb + OFF_DJ + s * 768 + which * 256 + q * 16, src);
        }
        CP_COMMIT();
    };

    auto buildP = [&](int s, int kt) {
        float* djd  = (float*)(sm + OFF_DJ + s * 768);
        float* dje1 = djd + 64;
        float* dje2 = djd + 128;
        u16* Ps = (u16*)(sm + OFF_P + s * SZ_P);
        unsigned word = g_adjbits[adjrow_base + (kt >> 5)];
#pragma unroll
        for (int c = 0; c < 16; c++) {
            int k0 = kb + 2 * c;
            float2 dd = *(float2*)&djd[k0];
            float2 e1 = *(float2*)&dje1[k0];
            float2 e2 = *(float2*)&dje2[k0];
            float x0 = srcv + dd.x;
            float p0 = (x0 > 0.f) ? E1s * e1.x : E2s * e2.x;
            if (!((word >> (2 * c)) & 1u)) p0 = 0.f;
            float x1 = srcv + dd.y;
            float p1 = (x1 > 0.f) ? E1s * e1.y : E2s * e2.y;
            if (!((word >> (2 * c + 1)) & 1u)) p1 = 0.f;
            __half2 hp = __floats2half2_rn(p0, p1);
            float2 rb = __half22float2(hp);       // rounded values for consistency
            psum += rb.x + rb.y;
            *(u32*)&Ps[rr * PST + k0] = *(u32*)&hp;
        }
    };

    auto do_mma = [&](int s) {
        u32 aP = smb + OFF_P + s * SZ_P + aoff;
        u32 bH = smb + OFF_B + (s * 2 + 0) * SZ_B + boff;
        u32 bL = smb + OFF_B + (s * 2 + 1) * SZ_B + boff;
#pragma unroll
        for (int ks = 0; ks < 4; ks++) {
            u32 ap[2][4];
#pragma unroll
            for (int mt = 0; mt < 2; mt++) {
                u32 off = (u32)((mt * 16 * PST + ks * 16) * 2);
                ldsm4(ap[mt], aP + off);
            }
            u32 bh[NG][4], bl[NG][4];
#pragma unroll
            for (int ng = 0; ng < NG; ng++) {
                u32 off = (u32)((ks * 16 * BST + ng * 16) * 2);
                ldsm4t(bh[ng], bH + off);
                ldsm4t(bl[ng], bL + off);
            }
            // pass 1: P*W_hi (16 distinct accumulators)
#pragma unroll
            for (int ng = 0; ng < NG; ng++)
#pragma unroll
                for (int mt = 0; mt < 2; mt++) {
                    mma_f16(acc[mt][2 * ng],     ap[mt], bh[ng]);
                    mma_f16(acc[mt][2 * ng + 1], ap[mt], bh[ng] + 2);
                }
            // pass 2: P*W_lo
#pragma unroll
            for (int ng = 0; ng < NG; ng++)
#pragma unroll
                for (int mt = 0; mt < 2; mt++) {
                    mma_f16(acc[mt][2 * ng],     ap[mt], bl[ng]);
                    mma_f16(acc[mt][2 * ng + 1], ap[mt], bl[ng] + 2);
                }
        }
    };

    stage(0, 0);
    CP_WAIT0();
    __syncthreads();
    buildP(0, 0);
    __syncthreads();

    for (int it = 0; it < NIT; ++it) {
        int s = it & 1;
        if (it + 1 < NIT) stage((it + 1) & 1, (it + 1) * BK);
        do_mma(s);
        if (it + 1 < NIT) {
            CP_WAIT0();
            buildP((it + 1) & 1, (it + 1) * BK);
        }
        __syncthreads();
    }

    {
        float tot = psum + __shfl_xor_sync(0xffffffffu, psum, 1);
        if (!half) rsum[rr] = tot;
    }
    __syncthreads();

    constexpr int CAT = HEADS * F;
    int r0 = mrow0 + (lane >> 2);
    int c0 = nb0 + (lane & 3) * 2;
#pragma unroll
    for (int mt = 0; mt < 2; mt++) {
        int ra = r0 + mt * 16, rb = ra + 8;
        float inva = 1.f / rsum[ra];
        float invb = 1.f / rsum[rb];
        float* outa = &hcat[(size_t)(m0 + ra) * CAT + h * F];
        float* outb = &hcat[(size_t)(m0 + rb) * CAT + h * F];
#pragma unroll
        for (int nt = 0; nt < NT; nt++) {
            int cc = c0 + nt * 8;
            float v0 = acc[mt][nt][0] * inva; v0 = v0 > 0.f ? v0 : expm1f(v0);
            float v1 = acc[mt][nt][1] * inva; v1 = v1 > 0.f ? v1 : expm1f(v1);
            float v2 = acc[mt][nt][2] * invb; v2 = v2 > 0.f ? v2 : expm1f(v2);
            float v3 = acc[mt][nt][3] * invb; v3 = v3 > 0.f ? v3 : expm1f(v3);
            *(float2*)&outa[cc] = make_float2(v0, v1);
            *(float2*)&outb[cc] = make_float2(v2, v3);
        }
    }
}

// ---------------- combine: out = relu( elu(A@LIN) + B@RES ) ----------------
__global__ __launch_bounds__(256) void combine_k(
    const float* __restrict__ A, int KA, const float* __restrict__ LIN,
    const float* __restrict__ B, int KB, const float* __restrict__ RES,
    float* __restrict__ out, int FOUT)
{
    int m0 = blockIdx.x * 64, n0 = blockIdx.y * 64;
    __shared__ float Xs[64][17];
    __shared__ __align__(16) float Ws[16][64];
    int tid = threadIdx.x, ty = tid / 16, tx = tid % 16;
    float acc[4][4] = {};
    for (int kt = 0; kt < KA; kt += 16) {
        int r = tid >> 2, c = (tid & 3) * 4;
        float4 xv = *(const float4*)&A[(size_t)(m0 + r) * KA + kt + c];
        Xs[r][c] = xv.x; Xs[r][c + 1] = xv.y; Xs[r][c + 2] = xv.z; Xs[r][c + 3] = xv.w;
        int r2 = tid >> 4, c2 = (tid & 15) * 4;
        *(float4*)&Ws[r2][c2] = *(const float4*)&LIN[(size_t)(kt + r2) * FOUT + n0 + c2];
        __syncthreads();
#pragma unroll
        for (int k = 0; k < 16; k++) {
            float a[4], b[4];
#pragma unroll
            for (int i = 0; i < 4; i++) a[i] = Xs[ty * 4 + i][k];
#pragma unroll
            for (int j = 0; j < 4; j++) b[j] = Ws[k][tx * 4 + j];
#pragma unroll
            for (int i = 0; i < 4; i++)
#pragma unroll
                for (int j = 0; j < 4; j++) acc[i][j] = fmaf(a[i], b[j], acc[i][j]);
        }
        __syncthreads();
    }
#pragma unroll
    for (int i = 0; i < 4; i++)
#pragma unroll
        for (int j = 0; j < 4; j++)
            acc[i][j] = acc[i][j] > 0.f ? acc[i][j] : expm1f(acc[i][j]);
    for (int kt = 0; kt < KB; kt += 16) {
        int r = tid >> 2, c = (tid & 3) * 4;
        float4 xv = *(const float4*)&B[(size_t)(m0 + r) * KB + kt + c];
        Xs[r][c] = xv.x; Xs[r][c + 1] = xv.y; Xs[r][c + 2] = xv.z; Xs[r][c + 3] = xv.w;
        int r2 = tid >> 4, c2 = (tid & 15) * 4;
        *(float4*)&Ws[r2][c2] = *(const float4*)&RES[(size_t)(kt + r2) * FOUT + n0 + c2];
        __syncthreads();
#pragma unroll
        for (int k = 0; k < 16; k++) {
            float a[4], b[4];
#pragma unroll
            for (int i = 0; i < 4; i++) a[i] = Xs[ty * 4 + i][k];
#pragma unroll
            for (int j = 0; j < 4; j++) b[j] = Ws[k][tx * 4 + j];
#pragma unroll
            for (int i = 0; i < 4; i++)
#pragma unroll
                for (int j = 0; j < 4; j++) acc[i][j] = fmaf(a[i], b[j], acc[i][j]);
        }
        __syncthreads();
    }
#pragma unroll
    for (int i = 0; i < 4; i++) {
        float4 v;
        v.x = fmaxf(acc[i][0], 0.f); v.y = fmaxf(acc[i][1], 0.f);
        v.z = fmaxf(acc[i][2], 0.f); v.w = fmaxf(acc[i][3], 0.f);
        *(float4*)&out[(size_t)(m0 + ty * 4 + i) * FOUT + n0 + tx * 4] = v;
    }
}

// ---------------- host launcher ----------------
extern "C" void kernel_launch(void* const* d_in, const int* in_sizes, int n_in,
                              void* d_out, int out_size)
{
    const float* x    = (const float*)d_in[0];
    const int*   adj  = (const int*)d_in[1];
    const float* W1   = (const float*)d_in[2];
    const float* a1s  = (const float*)d_in[3];
    const float* a1d  = (const float*)d_in[4];
    const float* lin1 = (const float*)d_in[5];
    const float* res1 = (const float*)d_in[6];
    const float* W2   = (const float*)d_in[7];
    const float* a2s  = (const float*)d_in[8];
    const float* a2d  = (const float*)d_in[9];
    const float* lin2 = (const float*)d_in[10];
    const float* res2 = (const float*)d_in[11];
    float* out = (float*)d_out;

    float *whbuf, *hcat, *h1;
    u16 *whh, *whl;
    void* maxenc;
    cudaGetSymbolAddress((void**)&whbuf, g_Whbuf);
    cudaGetSymbolAddress((void**)&hcat,  g_hcat);
    cudaGetSymbolAddress((void**)&h1,    g_h1);
    cudaGetSymbolAddress((void**)&whh,   g_WhH);
    cudaGetSymbolAddress((void**)&whl,   g_WhL);
    cudaGetSymbolAddress(&maxenc, g_maxenc);

    // smem: 2*SZ_P + 4*SZ_B + 2*768 + 512
    constexpr int SZP = 128 * 72 * 2;
    constexpr int SM1 = 2 * SZP + 4 * (64 * 136 * 2) + 2 * 768 + 512; // 108,544
    constexpr int SM2 = 2 * SZP + 4 * (64 * 72 * 2)  + 2 * 768 + 512; // 75,776
    cudaFuncSetAttribute(attn_mma_k<H1>, cudaFuncAttributeMaxDynamicSharedMemorySize, SM1);
    cudaFuncSetAttribute(attn_mma_k<H2>, cudaFuncAttributeMaxDynamicSharedMemorySize, SM2);

    pack_adj_k<<<NN * NN / 256, 256>>>(adj);

    // ---- layer 1 ----
    cudaMemsetAsync(maxenc, 0, HEADS * sizeof(unsigned));
    gemm_heads_k<<<dim3(NN / 64, H1 / 64, HEADS), 256>>>(x, W1, whbuf, whh, whl, IN_DIM, H1);
    srcdst_k<<<HEADS * NN * 32 / 256, 256>>>(whbuf, a1s, a1d, H1);
    exps_k<<<(HEADS * NN + 255) / 256, 256>>>();
    attn_mma_k<H1><<<dim3(NN / 128, HEADS), 256, SM1>>>(whh, whl, hcat);
    combine_k<<<dim3(NN / 64, H1 / 64), 256>>>(hcat, HEADS * H1, lin1, x, IN_DIM, res1, h1, H1);

    // ---- layer 2 ----
    cudaMemsetAsync(maxenc, 0, HEADS * sizeof(unsigned));
    gemm_heads_k<<<dim3(NN / 64, H2 / 64, HEADS), 256>>>(h1, W2, whbuf, whh, whl, H1, H2);
    srcdst_k<<<HEADS * NN * 32 / 256, 256>>>(whbuf, a2s, a2d, H2);
    exps_k<<<(HEADS * NN + 255) / 256, 256>>>();
    attn_mma_k<H2><<<dim3(NN / 128, HEADS), 256, SM2>>>(whh, whl, hcat);
    combine_k<<<dim3(NN / 64, H2 / 64), 256>>>(hcat, HEADS * H2, lin2, h1, H1, res2, out, H2);
}

// round 7
// speedup vs baseline: 2.1878x; 1.1401x over previous
#include <cuda_runtime.h>
#include <cuda_fp16.h>
#include <math.h>
#include <cstdint>

#define NN 3072
#define HEADS 4
#define IN_DIM 256
#define H1 128
#define H2 64
#define ADJW (NN/32)

typedef unsigned int u32;
typedef unsigned short u16;

// ---------------- scratch ----------------
__device__ unsigned g_adjbits[NN * ADJW];
__device__ float g_Whbuf[HEADS * NN * H1];
__device__ float g_src[HEADS * NN], g_dst[HEADS * NN];
__device__ float g_e1s[HEADS * NN], g_e2s[HEADS * NN];
__device__ float g_e1d[HEADS * NN], g_e2d[HEADS * NN];
__device__ unsigned g_maxenc[HEADS];
__device__ u16 g_WhH[HEADS * NN * H1];   // Wh fp16
__device__ float g_hcat[NN * HEADS * H1];
__device__ float g_h1[NN * H1];

// ---------------- helpers ----------------
__device__ __forceinline__ unsigned enc_f(float v) {
    int b = __float_as_int(v);
    return b >= 0 ? ((unsigned)b | 0x80000000u) : (unsigned)(~b);
}
__device__ __forceinline__ float dec_f(unsigned e) {
    return (e & 0x80000000u) ? __uint_as_float(e & 0x7fffffffu)
                             : __uint_as_float(~e);
}
__device__ __forceinline__ u32 smem_u32(const void* p) {
    u32 a;
    asm("{ .reg .u64 t; cvta.to.shared.u64 t, %1; cvt.u32.u64 %0, t; }" : "=r"(a) : "l"(p));
    return a;
}
__device__ __forceinline__ void ldsm4(u32* r, u32 addr) {
    asm volatile("ldmatrix.sync.aligned.m8n8.x4.shared.b16 {%0,%1,%2,%3}, [%4];"
                 : "=r"(r[0]), "=r"(r[1]), "=r"(r[2]), "=r"(r[3]) : "r"(addr));
}
__device__ __forceinline__ void ldsm4t(u32* r, u32 addr) {
    asm volatile("ldmatrix.sync.aligned.m8n8.x4.trans.shared.b16 {%0,%1,%2,%3}, [%4];"
                 : "=r"(r[0]), "=r"(r[1]), "=r"(r[2]), "=r"(r[3]) : "r"(addr));
}
__device__ __forceinline__ void mma_f16(float* d, const u32* a, const u32* b) {
    asm volatile(
        "mma.sync.aligned.m16n8k16.row.col.f32.f16.f16.f32 "
        "{%0,%1,%2,%3}, {%4,%5,%6,%7}, {%8,%9}, {%0,%1,%2,%3};"
        : "+f"(d[0]), "+f"(d[1]), "+f"(d[2]), "+f"(d[3])
        : "r"(a[0]), "r"(a[1]), "r"(a[2]), "r"(a[3]), "r"(b[0]), "r"(b[1]));
}
#define CP_ASYNC16(dst, src) asm volatile("cp.async.cg.shared.global [%0], [%1], 16;" :: "r"(dst), "l"(src))
#define CP_COMMIT()  asm volatile("cp.async.commit_group;" ::: "memory")
#define CP_WAIT0()   asm volatile("cp.async.wait_group 0;" ::: "memory")

// ---------------- adjacency bit-pack ----------------
__global__ void pack_adj_k(const int* __restrict__ adj) {
    int idx = blockIdx.x * blockDim.x + threadIdx.x;
    int v = adj[idx] > 0;
    unsigned m = __ballot_sync(0xffffffffu, v);
    if ((idx & 31) == 0) g_adjbits[idx >> 5] = m;
}

// ---------------- per-head GEMM: Wh[h] = X @ W[h]  (+ fused fp16 cast) ----------------
__global__ __launch_bounds__(256) void gemm_heads_k(
    const float* __restrict__ X, const float* __restrict__ W,
    float* __restrict__ out, u16* __restrict__ hi,
    int K, int F)
{
    int h = blockIdx.z;
    int m0 = blockIdx.x * 64, n0 = blockIdx.y * 64;
    const float* Wp = W + (size_t)h * K * F;
    size_t obase = (size_t)h * NN * F;
    __shared__ float Xs[64][17];
    __shared__ __align__(16) float Ws[16][64];
    int tid = threadIdx.x, ty = tid / 16, tx = tid % 16;
    float acc[4][4] = {};
    for (int kt = 0; kt < K; kt += 16) {
        int r = tid >> 2, c = (tid & 3) * 4;
        float4 xv = *(const float4*)&X[(size_t)(m0 + r) * K + kt + c];
        Xs[r][c] = xv.x; Xs[r][c + 1] = xv.y; Xs[r][c + 2] = xv.z; Xs[r][c + 3] = xv.w;
        int r2 = tid >> 4, c2 = (tid & 15) * 4;
        *(float4*)&Ws[r2][c2] = *(const float4*)&Wp[(size_t)(kt + r2) * F + n0 + c2];
        __syncthreads();
#pragma unroll
        for (int k = 0; k < 16; k++) {
            float a[4], b[4];
#pragma unroll
            for (int i = 0; i < 4; i++) a[i] = Xs[ty * 4 + i][k];
#pragma unroll
            for (int j = 0; j < 4; j++) b[j] = Ws[k][tx * 4 + j];
#pragma unroll
            for (int i = 0; i < 4; i++)
#pragma unroll
                for (int j = 0; j < 4; j++) acc[i][j] = fmaf(a[i], b[j], acc[i][j]);
        }
        __syncthreads();
    }
#pragma unroll
    for (int i = 0; i < 4; i++) {
        size_t o = obase + (size_t)(m0 + ty * 4 + i) * F + n0 + tx * 4;
        *(float4*)&out[o] = make_float4(acc[i][0], acc[i][1], acc[i][2], acc[i][3]);
        __half2 h01 = __floats2half2_rn(acc[i][0], acc[i][1]);
        __half2 h23 = __floats2half2_rn(acc[i][2], acc[i][3]);
        uint2 pk;
        pk.x = *(u32*)&h01;
        pk.y = *(u32*)&h23;
        *(uint2*)&hi[o] = pk;
    }
}

// ---------------- src/dst projections + per-head max(dst) ----------------
__global__ void srcdst_k(const float* __restrict__ Wh, const float* __restrict__ as,
                         const float* __restrict__ ad, int F)
{
    int w = (blockIdx.x * blockDim.x + threadIdx.x) >> 5;
    int lane = threadIdx.x & 31;
    if (w >= HEADS * NN) return;
    int h = w / NN;
    const float* row = Wh + (size_t)w * F;
    float ss = 0.f, dd = 0.f;
    for (int f = lane; f < F; f += 32) {
        float v = row[f];
        ss = fmaf(v, as[h * F + f], ss);
        dd = fmaf(v, ad[h * F + f], dd);
    }
#pragma unroll
    for (int o = 16; o; o >>= 1) {
        ss += __shfl_xor_sync(0xffffffffu, ss, o);
        dd += __shfl_xor_sync(0xffffffffu, dd, o);
    }
    if (!lane) {
        g_src[w] = ss; g_dst[w] = dd;
        atomicMax(&g_maxenc[h], enc_f(dd));
    }
}

// ---------------- factored exps ----------------
__global__ void exps_k() {
    int i = blockIdx.x * blockDim.x + threadIdx.x;
    if (i >= HEADS * NN) return;
    int h = i / NN;
    float s = g_src[i], d = g_dst[i];
    float x = s + dec_f(g_maxenc[h]);
    float c = x > 0.f ? x : 0.2f * x;
    g_e1s[i] = expf(s - c);
    g_e2s[i] = expf(0.2f * s - c);
    g_e1d[i] = expf(d);
    g_e2d[i] = expf(0.2f * d);
}

// ---------------- HMMA attention: D = P @ Wh (fp16 single-term) ----------------
// grid (NN/128, HEADS), block 256 (8 warps: 4 m-groups x 2 n-groups)
template <int F>
__global__ __launch_bounds__(256) void attn_mma_k(
    const u16* __restrict__ WhH, float* __restrict__ hcat)
{
    constexpr int BK = 64;
    constexpr int NIT = NN / BK;
    constexpr int PST = BK + 8;           // 72 halves
    constexpr int BST = F + 8;
    constexpr int NW = F / 2;
    constexpr int NT = NW / 8;            // 8 (F=128) / 4 (F=64)
    constexpr int NG = NT / 2;
    constexpr int VPR = F / 8;
    constexpr int SZ_P = 128 * PST * 2;
    constexpr int SZ_B = BK * BST * 2;
    constexpr int OFF_P = 0;              // [s]*SZ_P
    constexpr int OFF_B = 2 * SZ_P;       // [s]*SZ_B
    constexpr int OFF_DJ = OFF_B + 2 * SZ_B;
    constexpr int OFF_RS = OFF_DJ + 2 * 768;

    extern __shared__ char sm[];
    u32 smb = smem_u32(sm);
    float* rsum = (float*)(sm + OFF_RS);

    int tid = threadIdx.x, wid = tid >> 5, lane = tid & 31;
    int h = blockIdx.y, m0 = blockIdx.x * 128;
    int base = h * NN;
    const u16* WH = WhH + (size_t)base * F;

    // P-build role
    int rr = tid >> 1, half = tid & 1, kb = half * 32;
    float E1s = g_e1s[base + m0 + rr];
    float E2s = g_e2s[base + m0 + rr];
    float srcv = g_src[base + m0 + rr];
    float psum = 0.f;
    u32 adjrow_base = (u32)((m0 + rr) * ADJW) + half;

    // mma role
    int wm = wid & 3, wn = wid >> 2;
    int mrow0 = wm * 32, nb0 = wn * NW;
    float acc[2][NT][4];
#pragma unroll
    for (int i = 0; i < 2; i++)
#pragma unroll
        for (int j = 0; j < NT; j++)
#pragma unroll
            for (int q = 0; q < 4; q++) acc[i][j][q] = 0.f;

    u32 aoff = (u32)(((mrow0 + (lane & 15)) * PST + (lane >> 4) * 8) * 2);
    u32 boff = (u32)((((lane & 15)) * BST + nb0 + (lane >> 4) * 8) * 2);

    auto stage = [&](int s, int kt) {
        u32 bb = smb + OFF_B + s * SZ_B;
        const uint4* sh = (const uint4*)(WH + (size_t)kt * F);
#pragma unroll
        for (int i = tid; i < BK * VPR; i += 256) {
            int row = i / VPR, c = (i % VPR) * 8;
            CP_ASYNC16(bb + (u32)((row * BST + c) * 2), sh + i);
        }
        if (tid < 48) {
            int which = tid >> 4, q = tid & 15;
            const float* src = (which == 0 ? g_dst : which == 1 ? g_e1d : g_e2d)
                               + base + kt + q * 4;
            CP_ASYNC16(smb + OFF_DJ + s * 768 + which * 256 + q * 16, src);
        }
        CP_COMMIT();
    };

    auto buildP = [&](int s, int kt) {
        float* djd  = (float*)(sm + OFF_DJ + s * 768);
        float* dje1 = djd + 64;
        float* dje2 = djd + 128;
        u16* Ps = (u16*)(sm + OFF_P + s * SZ_P);
        unsigned word = g_adjbits[adjrow_base + (kt >> 5)];
#pragma unroll
        for (int c = 0; c < 16; c++) {
            int k0 = kb + 2 * c;
            float2 dd = *(float2*)&djd[k0];
            float2 e1 = *(float2*)&dje1[k0];
            float2 e2 = *(float2*)&dje2[k0];
            float x0 = srcv + dd.x;
            float p0 = (x0 > 0.f) ? E1s * e1.x : E2s * e2.x;
            if (!((word >> (2 * c)) & 1u)) p0 = 0.f;
            float x1 = srcv + dd.y;
            float p1 = (x1 > 0.f) ? E1s * e1.y : E2s * e2.y;
            if (!((word >> (2 * c + 1)) & 1u)) p1 = 0.f;
            __half2 hp = __floats2half2_rn(p0, p1);
            float2 rb = __half22float2(hp);       // rounded values keep num/den consistent
            psum += rb.x + rb.y;
            *(u32*)&Ps[rr * PST + k0] = *(u32*)&hp;
        }
    };

    auto do_mma = [&](int s) {
        u32 aP = smb + OFF_P + s * SZ_P + aoff;
        u32 bB = smb + OFF_B + s * SZ_B + boff;
#pragma unroll
        for (int ks = 0; ks < 4; ks++) {
            u32 ap[2][4];
#pragma unroll
            for (int mt = 0; mt < 2; mt++) {
                u32 off = (u32)((mt * 16 * PST + ks * 16) * 2);
                ldsm4(ap[mt], aP + off);
            }
            u32 bh[NG][4];
#pragma unroll
            for (int ng = 0; ng < NG; ng++) {
                u32 off = (u32)((ks * 16 * BST + ng * 16) * 2);
                ldsm4t(bh[ng], bB + off);
            }
#pragma unroll
            for (int ng = 0; ng < NG; ng++)
#pragma unroll
                for (int mt = 0; mt < 2; mt++) {
                    mma_f16(acc[mt][2 * ng],     ap[mt], bh[ng]);
                    mma_f16(acc[mt][2 * ng + 1], ap[mt], bh[ng] + 2);
                }
        }
    };

    stage(0, 0);
    CP_WAIT0();
    __syncthreads();
    buildP(0, 0);
    __syncthreads();

    for (int it = 0; it < NIT; ++it) {
        int s = it & 1;
        if (it + 1 < NIT) stage((it + 1) & 1, (it + 1) * BK);
        do_mma(s);
        if (it + 1 < NIT) {
            CP_WAIT0();
            buildP((it + 1) & 1, (it + 1) * BK);
        }
        __syncthreads();
    }

    {
        float tot = psum + __shfl_xor_sync(0xffffffffu, psum, 1);
        if (!half) rsum[rr] = tot;
    }
    __syncthreads();

    constexpr int CAT = HEADS * F;
    int r0 = mrow0 + (lane >> 2);
    int c0 = nb0 + (lane & 3) * 2;
#pragma unroll
    for (int mt = 0; mt < 2; mt++) {
        int ra = r0 + mt * 16, rb = ra + 8;
        float inva = 1.f / rsum[ra];
        float invb = 1.f / rsum[rb];
        float* outa = &hcat[(size_t)(m0 + ra) * CAT + h * F];
        float* outb = &hcat[(size_t)(m0 + rb) * CAT + h * F];
#pragma unroll
        for (int nt = 0; nt < NT; nt++) {
            int cc = c0 + nt * 8;
            float v0 = acc[mt][nt][0] * inva; v0 = v0 > 0.f ? v0 : expm1f(v0);
            float v1 = acc[mt][nt][1] * inva; v1 = v1 > 0.f ? v1 : expm1f(v1);
            float v2 = acc[mt][nt][2] * invb; v2 = v2 > 0.f ? v2 : expm1f(v2);
            float v3 = acc[mt][nt][3] * invb; v3 = v3 > 0.f ? v3 : expm1f(v3);
            *(float2*)&outa[cc] = make_float2(v0, v1);
            *(float2*)&outb[cc] = make_float2(v2, v3);
        }
    }
}

// ---------------- combine: out = relu( elu(A@LIN) + B@RES ) ----------------
__global__ __launch_bounds__(256) void combine_k(
    const float* __restrict__ A, int KA, const float* __restrict__ LIN,
    const float* __restrict__ B, int KB, const float* __restrict__ RES,
    float* __restrict__ out, int FOUT)
{
    int m0 = blockIdx.x * 64, n0 = blockIdx.y * 64;
    __shared__ float Xs[64][17];
    __shared__ __align__(16) float Ws[16][64];
    int tid = threadIdx.x, ty = tid / 16, tx = tid % 16;
    float acc[4][4] = {};
    for (int kt = 0; kt < KA; kt += 16) {
        int r = tid >> 2, c = (tid & 3) * 4;
        float4 xv = *(const float4*)&A[(size_t)(m0 + r) * KA + kt + c];
        Xs[r][c] = xv.x; Xs[r][c + 1] = xv.y; Xs[r][c + 2] = xv.z; Xs[r][c + 3] = xv.w;
        int r2 = tid >> 4, c2 = (tid & 15) * 4;
        *(float4*)&Ws[r2][c2] = *(const float4*)&LIN[(size_t)(kt + r2) * FOUT + n0 + c2];
        __syncthreads();
#pragma unroll
        for (int k = 0; k < 16; k++) {
            float a[4], b[4];
#pragma unroll
            for (int i = 0; i < 4; i++) a[i] = Xs[ty * 4 + i][k];
#pragma unroll
            for (int j = 0; j < 4; j++) b[j] = Ws[k][tx * 4 + j];
#pragma unroll
            for (int i = 0; i < 4; i++)
#pragma unroll
                for (int j = 0; j < 4; j++) acc[i][j] = fmaf(a[i], b[j], acc[i][j]);
        }
        __syncthreads();
    }
#pragma unroll
    for (int i = 0; i < 4; i++)
#pragma unroll
        for (int j = 0; j < 4; j++)
            acc[i][j] = acc[i][j] > 0.f ? acc[i][j] : expm1f(acc[i][j]);
    for (int kt = 0; kt < KB; kt += 16) {
        int r = tid >> 2, c = (tid & 3) * 4;
        float4 xv = *(const float4*)&B[(size_t)(m0 + r) * KB + kt + c];
        Xs[r][c] = xv.x; Xs[r][c + 1] = xv.y; Xs[r][c + 2] = xv.z; Xs[r][c + 3] = xv.w;
        int r2 = tid >> 4, c2 = (tid & 15) * 4;
        *(float4*)&Ws[r2][c2] = *(const float4*)&RES[(size_t)(kt + r2) * FOUT + n0 + c2];
        __syncthreads();
#pragma unroll
        for (int k = 0; k < 16; k++) {
            float a[4], b[4];
#pragma unroll
            for (int i = 0; i < 4; i++) a[i] = Xs[ty * 4 + i][k];
#pragma unroll
            for (int j = 0; j < 4; j++) b[j] = Ws[k][tx * 4 + j];
#pragma unroll
            for (int i = 0; i < 4; i++)
#pragma unroll
                for (int j = 0; j < 4; j++) acc[i][j] = fmaf(a[i], b[j], acc[i][j]);
        }
        __syncthreads();
    }
#pragma unroll
    for (int i = 0; i < 4; i++) {
        float4 v;
        v.x = fmaxf(acc[i][0], 0.f); v.y = fmaxf(acc[i][1], 0.f);
        v.z = fmaxf(acc[i][2], 0.f); v.w = fmaxf(acc[i][3], 0.f);
        *(float4*)&out[(size_t)(m0 + ty * 4 + i) * FOUT + n0 + tx * 4] = v;
    }
}

// ---------------- host launcher ----------------
extern "C" void kernel_launch(void* const* d_in, const int* in_sizes, int n_in,
                              void* d_out, int out_size)
{
    const float* x    = (const float*)d_in[0];
    const int*   adj  = (const int*)d_in[1];
    const float* W1   = (const float*)d_in[2];
    const float* a1s  = (const float*)d_in[3];
    const float* a1d  = (const float*)d_in[4];
    const float* lin1 = (const float*)d_in[5];
    const float* res1 = (const float*)d_in[6];
    const float* W2   = (const float*)d_in[7];
    const float* a2s  = (const float*)d_in[8];
    const float* a2d  = (const float*)d_in[9];
    const float* lin2 = (const float*)d_in[10];
    const float* res2 = (const float*)d_in[11];
    float* out = (float*)d_out;

    float *whbuf, *hcat, *h1;
    u16 *whh;
    void* maxenc;
    cudaGetSymbolAddress((void**)&whbuf, g_Whbuf);
    cudaGetSymbolAddress((void**)&hcat,  g_hcat);
    cudaGetSymbolAddress((void**)&h1,    g_h1);
    cudaGetSymbolAddress((void**)&whh,   g_WhH);
    cudaGetSymbolAddress(&maxenc, g_maxenc);

    // smem: 2*SZ_P + 2*SZ_B + 2*768 + 512
    constexpr int SZP = 128 * 72 * 2;
    constexpr int SM1 = 2 * SZP + 2 * (64 * 136 * 2) + 2 * 768 + 512; // 73,728
    constexpr int SM2 = 2 * SZP + 2 * (64 * 72 * 2)  + 2 * 768 + 512; // 57,344
    cudaFuncSetAttribute(attn_mma_k<H1>, cudaFuncAttributeMaxDynamicSharedMemorySize, SM1);
    cudaFuncSetAttribute(attn_mma_k<H2>, cudaFuncAttributeMaxDynamicSharedMemorySize, SM2);

    pack_adj_k<<<NN * NN / 256, 256>>>(adj);

    // ---- layer 1 ----
    cudaMemsetAsync(maxenc, 0, HEADS * sizeof(unsigned));
    gemm_heads_k<<<dim3(NN / 64, H1 / 64, HEADS), 256>>>(x, W1, whbuf, whh, IN_DIM, H1);
    srcdst_k<<<HEADS * NN * 32 / 256, 256>>>(whbuf, a1s, a1d, H1);
    exps_k<<<(HEADS * NN + 255) / 256, 256>>>();
    attn_mma_k<H1><<<dim3(NN / 128, HEADS), 256, SM1>>>(whh, hcat);
    combine_k<<<dim3(NN / 64, H1 / 64), 256>>>(hcat, HEADS * H1, lin1, x, IN_DIM, res1, h1, H1);

    // ---- layer 2 ----
    cudaMemsetAsync(maxenc, 0, HEADS * sizeof(unsigned));
    gemm_heads_k<<<dim3(NN / 64, H2 / 64, HEADS), 256>>>(h1, W2, whbuf, whh, H1, H2);
    srcdst_k<<<HEADS * NN * 32 / 256, 256>>>(whbuf, a2s, a2d, H2);
    exps_k<<<(HEADS * NN + 255) / 256, 256>>>();
    attn_mma_k<H2><<<dim3(NN / 128, HEADS), 256, SM2>>>(whh, hcat);
    combine_k<<<dim3(NN / 64, H2 / 64), 256>>>(hcat, HEADS * H2, lin2, h1, H1, res2, out, H2);
}